// round 8
// baseline (speedup 1.0000x reference)
#include <cuda_runtime.h>
#include <cuda_bf16.h>
#include <cstdint>

// Problem constants
#define Bb  2
#define Ss  2048
#define Dd  1024
#define Hh  16
#define HDd 64
#define MS  (Bb*Ss)          // 4096 rows
#define LN_EPS 1e-5f
#define GK 1024

// ---------------------------------------------------------------------------
// Scratch (device globals) — round-4 exact layout
// ---------------------------------------------------------------------------
__device__ float g_tmp[MS*Dd];          // pre-LN
__device__ __nv_bfloat16 g_ah[MS*Dd];   // input-activation hi (staging)
__device__ __nv_bfloat16 g_al[MS*Dd];
__device__ __nv_bfloat16 g_wh[Dd*Dd];   // weight^T hi [N][K]
__device__ __nv_bfloat16 g_wl[Dd*Dd];
__device__ __nv_bfloat16 g_qh[MS*Dd], g_ql[MS*Dd];
__device__ __nv_bfloat16 g_kh[MS*Dd], g_kl[MS*Dd];
__device__ __nv_bfloat16 g_vh[MS*Dd], g_vl[MS*Dd];
__device__ __nv_bfloat16 g_oh[MS*Dd], g_ol[MS*Dd];   // attention out split

// ---------------------------------------------------------------------------
// Helpers (round-4 exact)
// ---------------------------------------------------------------------------
__device__ __forceinline__ uint32_t smem_u32(const void* p) {
    uint32_t a;
    asm("{ .reg .u64 t; cvta.to.shared.u64 t, %1; cvt.u32.u64 %0, t; }"
        : "=r"(a) : "l"(p));
    return a;
}
__device__ __forceinline__ void cpa16(uint32_t s, const void* g) {
    asm volatile("cp.async.cg.shared.global [%0], [%1], 16;" :: "r"(s), "l"(g));
}
#define CPA_COMMIT() asm volatile("cp.async.commit_group;" ::: "memory")
#define CPA_WAIT0()  asm volatile("cp.async.wait_group 0;" ::: "memory")
#define CPA_WAIT1()  asm volatile("cp.async.wait_group 1;" ::: "memory")

__device__ __forceinline__ void ldm4(uint32_t a, uint32_t r[4]) {
    asm volatile("ldmatrix.sync.aligned.m8n8.x4.shared.b16 {%0,%1,%2,%3}, [%4];"
                 : "=r"(r[0]), "=r"(r[1]), "=r"(r[2]), "=r"(r[3]) : "r"(a));
}
__device__ __forceinline__ void ldm4t(uint32_t a, uint32_t r[4]) {
    asm volatile("ldmatrix.sync.aligned.m8n8.x4.trans.shared.b16 {%0,%1,%2,%3}, [%4];"
                 : "=r"(r[0]), "=r"(r[1]), "=r"(r[2]), "=r"(r[3]) : "r"(a));
}
__device__ __forceinline__ void mma16816(float d[4], const uint32_t a[4],
                                         uint32_t b0, uint32_t b1) {
    asm volatile(
        "mma.sync.aligned.m16n8k16.row.col.f32.bf16.bf16.f32 "
        "{%0,%1,%2,%3}, {%4,%5,%6,%7}, {%8,%9}, {%0,%1,%2,%3};"
        : "+f"(d[0]), "+f"(d[1]), "+f"(d[2]), "+f"(d[3])
        : "r"(a[0]), "r"(a[1]), "r"(a[2]), "r"(a[3]), "r"(b0), "r"(b1));
}
__device__ __forceinline__ void pack_split(float x, float y,
                                           uint32_t& hi, uint32_t& lo) {
    __nv_bfloat16 hx = __float2bfloat16(x), hy = __float2bfloat16(y);
    __nv_bfloat16 lx = __float2bfloat16(x - __bfloat162float(hx));
    __nv_bfloat16 ly = __float2bfloat16(y - __bfloat162float(hy));
    hi = (uint32_t)__bfloat16_as_ushort(hx) | ((uint32_t)__bfloat16_as_ushort(hy) << 16);
    lo = (uint32_t)__bfloat16_as_ushort(lx) | ((uint32_t)__bfloat16_as_ushort(ly) << 16);
}

#define GEMM_SMEM 81920

// ---------------------------------------------------------------------------
// Split-bf16 HMMA GEMM (round-4 exact live path)
// ---------------------------------------------------------------------------
__global__ __launch_bounds__(128)
void gemm_tc(const __nv_bfloat16* __restrict__ Ah, const __nv_bfloat16* __restrict__ Al,
             const __nv_bfloat16* __restrict__ Wh, const __nv_bfloat16* __restrict__ Wl,
             const float* __restrict__ resid, float* __restrict__ C,
             __nv_bfloat16* __restrict__ OH, __nv_bfloat16* __restrict__ OL)
{
    extern __shared__ __nv_bfloat16 S[];
    const int tid  = threadIdx.x;
    const int lane = tid & 31;
    const int wid  = tid >> 5;
    const int bm = blockIdx.y * 128;
    const int bn = blockIdx.x * 128;
    const int wm = (wid & 1) * 64;
    const int wn = (wid >> 1) * 64;

    const __nv_bfloat16* gA  = Ah + (size_t)bm * GK;
    const __nv_bfloat16* gAl = Al + (size_t)bm * GK;
    const __nv_bfloat16* gB  = Wh + (size_t)bn * GK;
    const __nv_bfloat16* gBl = Wl + (size_t)bn * GK;

    const uint32_t sbase = smem_u32(S);

    float d[4][8][4];
    #pragma unroll
    for (int i = 0; i < 4; i++)
        #pragma unroll
        for (int j = 0; j < 8; j++)
            #pragma unroll
            for (int e = 0; e < 4; e++) d[i][j][e] = 0.f;

    const uint32_t acb_row = (uint32_t)(lane & 15);
    const uint32_t acb_col = (uint32_t)((lane >> 4) * 8);

    {
        #pragma unroll
        for (int it = 0; it < 4; it++) {
            int f = tid + it * 128;
            int r = f >> 2;
            int u = f & 3;
            uint32_t so = sbase + (uint32_t)(r * 40 + u * 8) * 2;
            size_t go = (size_t)r * GK + u * 8;
            cpa16(so,          gA  + go);
            cpa16(so + 10240u, gAl + go);
            cpa16(so + 20480u, gB  + go);
            cpa16(so + 30720u, gBl + go);
        }
        CPA_COMMIT();
        CPA_WAIT0();
        __syncthreads();
    }

    for (int ic = 0; ic < 32; ic++) {
        const int st = ic & 1;
        if (ic + 1 < 32) {
            const int k0 = (ic + 1) * 32;
            const uint32_t sb2 = sbase + (uint32_t)((st ^ 1) * 40960);
            #pragma unroll
            for (int it = 0; it < 4; it++) {
                int f = tid + it * 128;
                int r = f >> 2;
                int u = f & 3;
                uint32_t so = sb2 + (uint32_t)(r * 40 + u * 8) * 2;
                size_t go = (size_t)r * GK + k0 + u * 8;
                cpa16(so,          gA  + go);
                cpa16(so + 10240u, gAl + go);
                cpa16(so + 20480u, gB  + go);
                cpa16(so + 30720u, gBl + go);
            }
        }
        CPA_COMMIT();

        const uint32_t sb = sbase + (uint32_t)(st * 40960);
        #pragma unroll
        for (int ks = 0; ks < 2; ks++) {
            const uint32_t cb = (uint32_t)(ks * 16) * 2 + acb_col * 2;

            uint32_t ah[4][4], bh[4][4];
            #pragma unroll
            for (int i = 0; i < 4; i++)
                ldm4(sb + (uint32_t)((wm + i * 16) + acb_row) * 80u + cb, ah[i]);
            #pragma unroll
            for (int nb = 0; nb < 4; nb++)
                ldm4(sb + 20480u + (uint32_t)((wn + nb * 16) + acb_row) * 80u + cb, bh[nb]);

            #pragma unroll
            for (int i = 0; i < 4; i++)
                #pragma unroll
                for (int nb = 0; nb < 4; nb++) {
                    mma16816(d[i][2*nb],     ah[i], bh[nb][0], bh[nb][2]);
                    mma16816(d[i][2*nb + 1], ah[i], bh[nb][1], bh[nb][3]);
                }
            {
                uint32_t bl[4][4];
                #pragma unroll
                for (int nb = 0; nb < 4; nb++)
                    ldm4(sb + 30720u + (uint32_t)((wn + nb * 16) + acb_row) * 80u + cb, bl[nb]);
                #pragma unroll
                for (int i = 0; i < 4; i++)
                    #pragma unroll
                    for (int nb = 0; nb < 4; nb++) {
                        mma16816(d[i][2*nb],     ah[i], bl[nb][0], bl[nb][2]);
                        mma16816(d[i][2*nb + 1], ah[i], bl[nb][1], bl[nb][3]);
                    }
            }
            {
                uint32_t al[4][4];
                #pragma unroll
                for (int i = 0; i < 4; i++)
                    ldm4(sb + 10240u + (uint32_t)((wm + i * 16) + acb_row) * 80u + cb, al[i]);
                #pragma unroll
                for (int i = 0; i < 4; i++)
                    #pragma unroll
                    for (int nb = 0; nb < 4; nb++) {
                        mma16816(d[i][2*nb],     al[i], bh[nb][0], bh[nb][2]);
                        mma16816(d[i][2*nb + 1], al[i], bh[nb][1], bh[nb][3]);
                    }
            }
        }
        CPA_WAIT0();
        __syncthreads();
    }

    const int er = bm + wm + (lane >> 2);
    const int ec = bn + wn + (lane & 3) * 2;
    #pragma unroll
    for (int i = 0; i < 4; i++) {
        const int r1 = er + i * 16;
        #pragma unroll
        for (int jj = 0; jj < 8; jj++) {
            const int c = ec + jj * 8;
            size_t o0 = (size_t)r1 * GK + c;
            size_t o1 = (size_t)(r1 + 8) * GK + c;
            if (OH) {
                uint32_t hu, lu;
                pack_split(d[i][jj][0], d[i][jj][1], hu, lu);
                *(uint32_t*)(OH + o0) = hu;
                *(uint32_t*)(OL + o0) = lu;
                pack_split(d[i][jj][2], d[i][jj][3], hu, lu);
                *(uint32_t*)(OH + o1) = hu;
                *(uint32_t*)(OL + o1) = lu;
            } else {
                float2 v0 = make_float2(d[i][jj][0], d[i][jj][1]);
                float2 v1 = make_float2(d[i][jj][2], d[i][jj][3]);
                if (resid) {
                    float2 q0 = *(const float2*)(resid + o0);
                    float2 q1 = *(const float2*)(resid + o1);
                    v0.x += q0.x; v0.y += q0.y;
                    v1.x += q1.x; v1.y += q1.y;
                }
                *(float2*)(C + o0) = v0;
                *(float2*)(C + o1) = v1;
            }
        }
    }
}

// ---------------------------------------------------------------------------
// fp32 -> bf16 hi/lo split (round-4 exact)
// ---------------------------------------------------------------------------
__global__ __launch_bounds__(256) void conv_act(
    const float* __restrict__ X, __nv_bfloat16* __restrict__ H,
    __nv_bfloat16* __restrict__ L)
{
    int i = blockIdx.x * 256 + threadIdx.x;
    float4 v = ((const float4*)X)[i];
    float vv[4] = {v.x, v.y, v.z, v.w};
    __nv_bfloat16 h[4], l[4];
    #pragma unroll
    for (int j = 0; j < 4; j++) {
        h[j] = __float2bfloat16(vv[j]);
        l[j] = __float2bfloat16(vv[j] - __bfloat162float(h[j]));
    }
    uint64_t hp, lp;
    memcpy(&hp, h, 8); memcpy(&lp, l, 8);
    ((uint64_t*)H)[i] = hp;
    ((uint64_t*)L)[i] = lp;
}

// ---------------------------------------------------------------------------
// W [K][N] fp32 -> W^T hi/lo bf16 [N][K] (round-4 exact)
// ---------------------------------------------------------------------------
__global__ __launch_bounds__(256) void conv_wt(
    const float* __restrict__ W, __nv_bfloat16* __restrict__ TH,
    __nv_bfloat16* __restrict__ TL)
{
    __shared__ float t[32][33];
    const int bxn = blockIdx.x * 32;
    const int byk = blockIdx.y * 32;
    const int tx = threadIdx.x & 31;
    const int ty4 = (threadIdx.x >> 5) * 4;

    #pragma unroll
    for (int j = 0; j < 4; j++)
        t[ty4 + j][tx] = W[(size_t)(byk + ty4 + j) * Dd + bxn + tx];
    __syncthreads();

    #pragma unroll
    for (int j = 0; j < 4; j++) {
        float x = t[tx][ty4 + j];
        __nv_bfloat16 h = __float2bfloat16(x);
        __nv_bfloat16 l = __float2bfloat16(x - __bfloat162float(h));
        size_t o = (size_t)(bxn + ty4 + j) * Dd + byk + tx;
        TH[o] = h;
        TL[o] = l;
    }
}

// ---------------------------------------------------------------------------
// HMMA flash attention (round-4 exact: Q frags in registers, no launch cap)
// ---------------------------------------------------------------------------
#define AT_ROWB   144
#define AT_TILE_B (64 * AT_ROWB)      // 9216
#define AT_STAGE_B (4 * AT_TILE_B)    // 36864
#define ATTN2_SMEM (2 * AT_STAGE_B)   // 73728
#define CS 0.18033688011112042f      // log2(e)/8

__global__ __launch_bounds__(256) void attn_tc(
    const __nv_bfloat16* __restrict__ Qh, const __nv_bfloat16* __restrict__ Ql,
    const __nv_bfloat16* __restrict__ Kh, const __nv_bfloat16* __restrict__ Kl,
    const __nv_bfloat16* __restrict__ Vh, const __nv_bfloat16* __restrict__ Vl,
    __nv_bfloat16* __restrict__ Oh, __nv_bfloat16* __restrict__ Ol)
{
    extern __shared__ char smc[];
    const int tid = threadIdx.x;
    const int lane = tid & 31;
    const int w = tid >> 5;
    const int bx = blockIdx.x, h = blockIdx.y, b = blockIdx.z;
    const int q0 = bx * 128;
    const uint32_t sb = smem_u32(smc);
    const size_t headoff = (size_t)b * Ss * Dd + (size_t)h * HDd;

    // ---- Q tiles -> SMEM (hi @0, lo @18432), then frags -> registers
    {
        const __nv_bfloat16* gq  = Qh + headoff + (size_t)q0 * Dd;
        const __nv_bfloat16* gql = Ql + headoff + (size_t)q0 * Dd;
        #pragma unroll
        for (int it = 0; it < 4; it++) {
            int f = tid + it * 256;          // 0..1023
            int r = f >> 3, ch = f & 7;
            uint32_t so = sb + (uint32_t)(r * AT_ROWB + ch * 16);
            size_t go = (size_t)r * Dd + ch * 8;
            cpa16(so, gq + go);
            cpa16(so + 18432u, gql + go);
        }
        CPA_COMMIT();
        CPA_WAIT0();
    }
    __syncthreads();

    uint32_t qh[4][4], ql[4][4];
    {
        uint32_t base = sb + (uint32_t)((16 * w + (lane & 15)) * AT_ROWB
                                        + (lane >> 4) * 16);
        #pragma unroll
        for (int c = 0; c < 4; c++) {
            ldm4(base + (uint32_t)(c * 32), qh[c]);
            ldm4(base + 18432u + (uint32_t)(c * 32), ql[c]);
        }
    }
    __syncthreads();   // done with Q smem; K/V loads may overwrite

    float oacc[8][4];
    #pragma unroll
    for (int i = 0; i < 8; i++)
        #pragma unroll
        for (int e = 0; e < 4; e++) oacc[i][e] = 0.f;
    float m0 = -1e30f, m1 = -1e30f, l0 = 0.f, l1 = 0.f;
    const int r0g = q0 + 16 * w + (lane >> 2);
    const int r1g = r0g + 8;

    const int nkt = 2 * bx + 2;
    const __nv_bfloat16 *gkh = Kh + headoff, *gkl = Kl + headoff;
    const __nv_bfloat16 *gvh = Vh + headoff, *gvl = Vl + headoff;

    // prologue: tile 0 -> stage 0
    #pragma unroll
    for (int it = 0; it < 2; it++) {
        int f = tid + it * 256;              // 0..511
        int r = f >> 3, ch = f & 7;
        uint32_t so = sb + (uint32_t)(r * AT_ROWB + ch * 16);
        size_t go = (size_t)r * Dd + ch * 8;
        cpa16(so,                  gkh + go);
        cpa16(so + AT_TILE_B,      gkl + go);
        cpa16(so + 2 * AT_TILE_B,  gvh + go);
        cpa16(so + 3 * AT_TILE_B,  gvl + go);
    }
    CPA_COMMIT();

    for (int kt = 0; kt < nkt; kt++) {
        __syncthreads();
        if (kt + 1 < nkt) {
            const uint32_t st2 = sb + (uint32_t)(((kt + 1) & 1) * AT_STAGE_B);
            const size_t kb = (size_t)(kt + 1) * 64 * Dd;
            #pragma unroll
            for (int it = 0; it < 2; it++) {
                int f = tid + it * 256;
                int r = f >> 3, ch = f & 7;
                uint32_t so = st2 + (uint32_t)(r * AT_ROWB + ch * 16);
                size_t go = kb + (size_t)r * Dd + ch * 8;
                cpa16(so,                 gkh + go);
                cpa16(so + AT_TILE_B,     gkl + go);
                cpa16(so + 2 * AT_TILE_B, gvh + go);
                cpa16(so + 3 * AT_TILE_B, gvl + go);
            }
            CPA_COMMIT();
            CPA_WAIT1();
        } else {
            CPA_WAIT0();
        }
        __syncthreads();

        const int k0 = kt * 64;
        const bool active = (k0 <= q0 + 16 * w + 15);   // warp-uniform
        if (active) {
            const uint32_t stg = sb + (uint32_t)((kt & 1) * AT_STAGE_B);
            float sacc[8][4];
            #pragma unroll
            for (int i = 0; i < 8; i++)
                #pragma unroll
                for (int e = 0; e < 4; e++) sacc[i][e] = 0.f;

            const uint32_t lb = stg + (uint32_t)((lane & 15) * AT_ROWB
                                                 + (lane >> 4) * 16);
            #pragma unroll
            for (int c = 0; c < 4; c++) {
                #pragma unroll
                for (int g = 0; g < 4; g++) {
                    uint32_t kh4[4], kl4[4];
                    uint32_t a = lb + (uint32_t)(g * 16 * AT_ROWB + c * 32);
                    ldm4(a, kh4);
                    ldm4(a + AT_TILE_B, kl4);
                    mma16816(sacc[2*g],   qh[c], kh4[0], kh4[2]);
                    mma16816(sacc[2*g+1], qh[c], kh4[1], kh4[3]);
                    mma16816(sacc[2*g],   qh[c], kl4[0], kl4[2]);
                    mma16816(sacc[2*g+1], qh[c], kl4[1], kl4[3]);
                    mma16816(sacc[2*g],   ql[c], kh4[0], kh4[2]);
                    mma16816(sacc[2*g+1], ql[c], kh4[1], kh4[3]);
                }
            }

            if (k0 + 63 > q0 + 16 * w) {
                #pragma unroll
                for (int nb = 0; nb < 8; nb++) {
                    int col = k0 + nb * 8 + (lane & 3) * 2;
                    if (col     > r0g) sacc[nb][0] = -1e30f;
                    if (col + 1 > r0g) sacc[nb][1] = -1e30f;
                    if (col     > r1g) sacc[nb][2] = -1e30f;
                    if (col + 1 > r1g) sacc[nb][3] = -1e30f;
                }
            }

            float mx0 = -1e30f, mx1 = -1e30f;
            #pragma unroll
            for (int nb = 0; nb < 8; nb++) {
                mx0 = fmaxf(mx0, fmaxf(sacc[nb][0], sacc[nb][1]));
                mx1 = fmaxf(mx1, fmaxf(sacc[nb][2], sacc[nb][3]));
            }
            mx0 = fmaxf(mx0, __shfl_xor_sync(0xffffffffu, mx0, 1));
            mx0 = fmaxf(mx0, __shfl_xor_sync(0xffffffffu, mx0, 2));
            mx1 = fmaxf(mx1, __shfl_xor_sync(0xffffffffu, mx1, 1));
            mx1 = fmaxf(mx1, __shfl_xor_sync(0xffffffffu, mx1, 2));
            const float nm0 = fmaxf(m0, mx0), nm1 = fmaxf(m1, mx1);
            const float a0 = exp2f((m0 - nm0) * CS);
            const float a1 = exp2f((m1 - nm1) * CS);
            m0 = nm0; m1 = nm1;
            const float c0 = nm0 * CS, c1 = nm1 * CS;
            float s0 = 0.f, s1 = 0.f;
            #pragma unroll
            for (int nb = 0; nb < 8; nb++) {
                float p0 = exp2f(fmaf(sacc[nb][0], CS, -c0));
                float p1 = exp2f(fmaf(sacc[nb][1], CS, -c0));
                float p2 = exp2f(fmaf(sacc[nb][2], CS, -c1));
                float p3 = exp2f(fmaf(sacc[nb][3], CS, -c1));
                sacc[nb][0] = p0; sacc[nb][1] = p1;
                sacc[nb][2] = p2; sacc[nb][3] = p3;
                s0 += p0 + p1;
                s1 += p2 + p3;
            }
            s0 += __shfl_xor_sync(0xffffffffu, s0, 1);
            s0 += __shfl_xor_sync(0xffffffffu, s0, 2);
            s1 += __shfl_xor_sync(0xffffffffu, s1, 1);
            s1 += __shfl_xor_sync(0xffffffffu, s1, 2);
            l0 = l0 * a0 + s0;
            l1 = l1 * a1 + s1;
            #pragma unroll
            for (int i = 0; i < 8; i++) {
                oacc[i][0] *= a0; oacc[i][1] *= a0;
                oacc[i][2] *= a1; oacc[i][3] *= a1;
            }

            #pragma unroll
            for (int j = 0; j < 4; j++) {
                uint32_t pa[4], pl[4];
                pack_split(sacc[2*j][0],   sacc[2*j][1],   pa[0], pl[0]);
                pack_split(sacc[2*j][2],   sacc[2*j][3],   pa[1], pl[1]);
                pack_split(sacc[2*j+1][0], sacc[2*j+1][1], pa[2], pl[2]);
                pack_split(sacc[2*j+1][2], sacc[2*j+1][3], pa[3], pl[3]);
                const uint32_t vb = stg + 2 * AT_TILE_B
                    + (uint32_t)((16 * j + (lane & 15)) * AT_ROWB + (lane >> 4) * 16);
                #pragma unroll
                for (int dp = 0; dp < 4; dp++) {
                    uint32_t vh4[4], vl4[4];
                    ldm4t(vb + (uint32_t)(dp * 32), vh4);
                    ldm4t(vb + AT_TILE_B + (uint32_t)(dp * 32), vl4);
                    mma16816(oacc[2*dp],   pa, vh4[0], vh4[1]);
                    mma16816(oacc[2*dp+1], pa, vh4[2], vh4[3]);
                    mma16816(oacc[2*dp],   pa, vl4[0], vl4[1]);
                    mma16816(oacc[2*dp+1], pa, vl4[2], vl4[3]);
                    mma16816(oacc[2*dp],   pl, vh4[0], vh4[1]);
                    mma16816(oacc[2*dp+1], pl, vh4[2], vh4[3]);
                }
            }
        }
    }

    const float i0 = 1.f / l0, i1 = 1.f / l1;
    const size_t ro0 = (size_t)b * Ss * Dd + (size_t)r0g * Dd + (size_t)h * HDd;
    const size_t ro1 = ro0 + 8 * Dd;
    #pragma unroll
    for (int nb = 0; nb < 8; nb++) {
        const int dcol = nb * 8 + (lane & 3) * 2;
        uint32_t hu, lu;
        pack_split(oacc[nb][0] * i0, oacc[nb][1] * i0, hu, lu);
        *(uint32_t*)(Oh + ro0 + dcol) = hu;
        *(uint32_t*)(Ol + ro0 + dcol) = lu;
        pack_split(oacc[nb][2] * i1, oacc[nb][3] * i1, hu, lu);
        *(uint32_t*)(Oh + ro1 + dcol) = hu;
        *(uint32_t*)(Ol + ro1 + dcol) = lu;
    }
}

// ---------------------------------------------------------------------------
// LayerNorm over last dim (1024) — round-4 exact
// ---------------------------------------------------------------------------
__global__ __launch_bounds__(256) void ln_kernel(
    const float* __restrict__ X, const float* __restrict__ gamma,
    const float* __restrict__ beta, float* __restrict__ Y)
{
    const int row = blockIdx.x;
    const int t = threadIdx.x;
    const float4 v = ((const float4*)(X + (size_t)row * Dd))[t];

    float s  = v.x + v.y + v.z + v.w;
    float ss = v.x * v.x + v.y * v.y + v.z * v.z + v.w * v.w;
    #pragma unroll
    for (int o = 16; o > 0; o >>= 1) {
        s  += __shfl_xor_sync(0xffffffffu, s,  o);
        ss += __shfl_xor_sync(0xffffffffu, ss, o);
    }
    __shared__ float sh[8][2];
    if ((t & 31) == 0) { sh[t >> 5][0] = s; sh[t >> 5][1] = ss; }
    __syncthreads();
    float ts = 0.f, tss = 0.f;
    #pragma unroll
    for (int i = 0; i < 8; i++) { ts += sh[i][0]; tss += sh[i][1]; }

    const float mu  = ts * (1.0f / Dd);
    const float var = tss * (1.0f / Dd) - mu * mu;
    const float inv = rsqrtf(var + LN_EPS);

    const float4 gg = ((const float4*)gamma)[t];
    const float4 bb = ((const float4*)beta)[t];
    float4 y;
    y.x = (v.x - mu) * inv * gg.x + bb.x;
    y.y = (v.y - mu) * inv * gg.y + bb.y;
    y.z = (v.z - mu) * inv * gg.z + bb.z;
    y.w = (v.w - mu) * inv * gg.w + bb.w;
    ((float4*)(Y + (size_t)row * Dd))[t] = y;
}

// ---------------------------------------------------------------------------
// Launch — round-4 exact structure.
// Inputs: q, k, v, wq, wk, wv, wo, gamma, beta, mask (causal; unused).
// ---------------------------------------------------------------------------
extern "C" void kernel_launch(void* const* d_in, const int* in_sizes, int n_in,
                              void* d_out, int out_size)
{
    const float* q     = (const float*)d_in[0];
    const float* k     = (const float*)d_in[1];
    const float* v     = (const float*)d_in[2];
    const float* wq    = (const float*)d_in[3];
    const float* wk    = (const float*)d_in[4];
    const float* wv    = (const float*)d_in[5];
    const float* wo    = (const float*)d_in[6];
    const float* gamma = (const float*)d_in[7];
    const float* beta  = (const float*)d_in[8];
    float* out = (float*)d_out;

    float* gtmp;
    __nv_bfloat16 *gah, *gal, *gwh, *gwl;
    __nv_bfloat16 *gqh, *gql, *gkh, *gkl, *gvh, *gvl, *goh, *gol;
    cudaGetSymbolAddress((void**)&gtmp, g_tmp);
    cudaGetSymbolAddress((void**)&gah,  g_ah);
    cudaGetSymbolAddress((void**)&gal,  g_al);
    cudaGetSymbolAddress((void**)&gwh,  g_wh);
    cudaGetSymbolAddress((void**)&gwl,  g_wl);
    cudaGetSymbolAddress((void**)&gqh,  g_qh);
    cudaGetSymbolAddress((void**)&gql,  g_ql);
    cudaGetSymbolAddress((void**)&gkh,  g_kh);
    cudaGetSymbolAddress((void**)&gkl,  g_kl);
    cudaGetSymbolAddress((void**)&gvh,  g_vh);
    cudaGetSymbolAddress((void**)&gvl,  g_vl);
    cudaGetSymbolAddress((void**)&goh,  g_oh);
    cudaGetSymbolAddress((void**)&gol,  g_ol);

    cudaFuncSetAttribute(gemm_tc,
                         cudaFuncAttributeMaxDynamicSharedMemorySize, GEMM_SMEM);
    cudaFuncSetAttribute(attn_tc,
                         cudaFuncAttributeMaxDynamicSharedMemorySize, ATTN2_SMEM);

    const dim3 blk256(256);
    const dim3 blk128(128);
    const dim3 gconv(MS * Dd / 4 / 256);
    const dim3 gwt(Dd / 32, Dd / 32);
    const dim3 ggemm(Dd / 128, MS / 128);     // (8, 32)

    // Q projection -> split
    conv_wt<<<gwt, blk256>>>(wq, gwh, gwl);
    conv_act<<<gconv, blk256>>>(q, gah, gal);
    gemm_tc<<<ggemm, blk128, GEMM_SMEM>>>(gah, gal, gwh, gwl, nullptr, nullptr, gqh, gql);
    // K projection -> split
    conv_wt<<<gwt, blk256>>>(wk, gwh, gwl);
    conv_act<<<gconv, blk256>>>(k, gah, gal);
    gemm_tc<<<ggemm, blk128, GEMM_SMEM>>>(gah, gal, gwh, gwl, nullptr, nullptr, gkh, gkl);
    // V projection -> split
    conv_wt<<<gwt, blk256>>>(wv, gwh, gwl);
    conv_act<<<gconv, blk256>>>(v, gah, gal);
    gemm_tc<<<ggemm, blk128, GEMM_SMEM>>>(gah, gal, gwh, gwl, nullptr, nullptr, gvh, gvl);

    // flash attention (tensor cores) -> split output
    dim3 ga(Ss / 128, Hh, Bb);                // (16, 16, 2)
    attn_tc<<<ga, blk256, ATTN2_SMEM>>>(gqh, gql, gkh, gkl, gvh, gvl, goh, gol);

    // output projection + residual (fp32 out)
    conv_wt<<<gwt, blk256>>>(wo, gwh, gwl);
    gemm_tc<<<ggemm, blk128, GEMM_SMEM>>>(goh, gol, gwh, gwl, q, gtmp, nullptr, nullptr);

    // LayerNorm
    ln_kernel<<<MS, blk256>>>(gtmp, gamma, beta, out);
}

// round 9
// speedup vs baseline: 1.0278x; 1.0278x over previous
#include <cuda_runtime.h>
#include <cuda_bf16.h>
#include <cstdint>

// Problem constants
#define Bb  2
#define Ss  2048
#define Dd  1024
#define Hh  16
#define HDd 64
#define MS  (Bb*Ss)          // 4096 rows
#define LN_EPS 1e-5f
#define GK 1024

// ---------------------------------------------------------------------------
// Scratch (device globals)
// ---------------------------------------------------------------------------
__device__ float g_tmp[MS*Dd];          // pre-LN
__device__ __nv_bfloat16 g_ah[MS*Dd];   // activation staging hi
__device__ __nv_bfloat16 g_al[MS*Dd];
__device__ __nv_bfloat16 g_wh[Dd*Dd];   // weight^T hi [N][K]
__device__ __nv_bfloat16 g_wl[Dd*Dd];
__device__ __nv_bfloat16 g_qh[MS*Dd], g_ql[MS*Dd];
__device__ __nv_bfloat16 g_kh[MS*Dd], g_kl[MS*Dd];
__device__ __nv_bfloat16 g_vh[MS*Dd], g_vl[MS*Dd];
__device__ __nv_bfloat16 g_oh[MS*Dd], g_ol[MS*Dd];

// ---------------------------------------------------------------------------
// Helpers
// ---------------------------------------------------------------------------
__device__ __forceinline__ uint32_t smem_u32(const void* p) {
    uint32_t a;
    asm("{ .reg .u64 t; cvta.to.shared.u64 t, %1; cvt.u32.u64 %0, t; }"
        : "=r"(a) : "l"(p));
    return a;
}
__device__ __forceinline__ void cpa16(uint32_t s, const void* g) {
    asm volatile("cp.async.cg.shared.global [%0], [%1], 16;" :: "r"(s), "l"(g));
}
#define CPA_COMMIT() asm volatile("cp.async.commit_group;" ::: "memory")
#define CPA_WAIT0()  asm volatile("cp.async.wait_group 0;" ::: "memory")
#define CPA_WAIT1()  asm volatile("cp.async.wait_group 1;" ::: "memory")

__device__ __forceinline__ void ldm4(uint32_t a, uint32_t r[4]) {
    asm volatile("ldmatrix.sync.aligned.m8n8.x4.shared.b16 {%0,%1,%2,%3}, [%4];"
                 : "=r"(r[0]), "=r"(r[1]), "=r"(r[2]), "=r"(r[3]) : "r"(a));
}
__device__ __forceinline__ void ldm4t(uint32_t a, uint32_t r[4]) {
    asm volatile("ldmatrix.sync.aligned.m8n8.x4.trans.shared.b16 {%0,%1,%2,%3}, [%4];"
                 : "=r"(r[0]), "=r"(r[1]), "=r"(r[2]), "=r"(r[3]) : "r"(a));
}
__device__ __forceinline__ void mma16816(float d[4], const uint32_t a[4],
                                         uint32_t b0, uint32_t b1) {
    asm volatile(
        "mma.sync.aligned.m16n8k16.row.col.f32.bf16.bf16.f32 "
        "{%0,%1,%2,%3}, {%4,%5,%6,%7}, {%8,%9}, {%0,%1,%2,%3};"
        : "+f"(d[0]), "+f"(d[1]), "+f"(d[2]), "+f"(d[3])
        : "r"(a[0]), "r"(a[1]), "r"(a[2]), "r"(a[3]), "r"(b0), "r"(b1));
}
__device__ __forceinline__ void pack_split(float x, float y,
                                           uint32_t& hi, uint32_t& lo) {
    __nv_bfloat16 hx = __float2bfloat16(x), hy = __float2bfloat16(y);
    __nv_bfloat16 lx = __float2bfloat16(x - __bfloat162float(hx));
    __nv_bfloat16 ly = __float2bfloat16(y - __bfloat162float(hy));
    hi = (uint32_t)__bfloat16_as_ushort(hx) | ((uint32_t)__bfloat16_as_ushort(hy) << 16);
    lo = (uint32_t)__bfloat16_as_ushort(lx) | ((uint32_t)__bfloat16_as_ushort(ly) << 16);
}

#define GEMM_SMEM 81920

// ---------------------------------------------------------------------------
// Split-bf16 HMMA GEMM — 256 threads, 128x128 CTA tile, 64x32 warp tile.
// 8 warps (2 m x 4 n), 64 fp32 accums/thread -> ~125 regs -> 2 CTAs/SM.
// Same smem layout & 2-stage cp.async pipeline as the proven 128-thr version.
// ---------------------------------------------------------------------------
__global__ __launch_bounds__(256, 2)
void gemm_tc(const __nv_bfloat16* __restrict__ Ah, const __nv_bfloat16* __restrict__ Al,
             const __nv_bfloat16* __restrict__ Wh, const __nv_bfloat16* __restrict__ Wl,
             const float* __restrict__ resid, float* __restrict__ C,
             __nv_bfloat16* __restrict__ OH, __nv_bfloat16* __restrict__ OL)
{
    extern __shared__ __nv_bfloat16 S[];
    const int tid  = threadIdx.x;
    const int lane = tid & 31;
    const int wid  = tid >> 5;            // 0..7
    const int bm = blockIdx.y * 128;
    const int bn = blockIdx.x * 128;
    const int wm = (wid & 1) * 64;        // 2 warp rows
    const int wn = (wid >> 1) * 32;       // 4 warp cols

    const __nv_bfloat16* gA  = Ah + (size_t)bm * GK;
    const __nv_bfloat16* gAl = Al + (size_t)bm * GK;
    const __nv_bfloat16* gB  = Wh + (size_t)bn * GK;
    const __nv_bfloat16* gBl = Wl + (size_t)bn * GK;

    const uint32_t sbase = smem_u32(S);

    float d[4][4][4];
    #pragma unroll
    for (int i = 0; i < 4; i++)
        #pragma unroll
        for (int j = 0; j < 4; j++)
            #pragma unroll
            for (int e = 0; e < 4; e++) d[i][j][e] = 0.f;

    const uint32_t acb_row = (uint32_t)(lane & 15);
    const uint32_t acb_col = (uint32_t)((lane >> 4) * 8);

    // prologue: stage 0, k0 = 0 (512 cpa16 per matrix, 2 its x 256 thr)
    {
        #pragma unroll
        for (int it = 0; it < 2; it++) {
            int f = tid + it * 256;
            int r = f >> 2;
            int u = f & 3;
            uint32_t so = sbase + (uint32_t)(r * 40 + u * 8) * 2;
            size_t go = (size_t)r * GK + u * 8;
            cpa16(so,          gA  + go);
            cpa16(so + 10240u, gAl + go);
            cpa16(so + 20480u, gB  + go);
            cpa16(so + 30720u, gBl + go);
        }
        CPA_COMMIT();
        CPA_WAIT0();
        __syncthreads();
    }

    for (int ic = 0; ic < 32; ic++) {
        const int st = ic & 1;
        if (ic + 1 < 32) {
            const int k0 = (ic + 1) * 32;
            const uint32_t sb2 = sbase + (uint32_t)((st ^ 1) * 40960);
            #pragma unroll
            for (int it = 0; it < 2; it++) {
                int f = tid + it * 256;
                int r = f >> 2;
                int u = f & 3;
                uint32_t so = sb2 + (uint32_t)(r * 40 + u * 8) * 2;
                size_t go = (size_t)r * GK + k0 + u * 8;
                cpa16(so,          gA  + go);
                cpa16(so + 10240u, gAl + go);
                cpa16(so + 20480u, gB  + go);
                cpa16(so + 30720u, gBl + go);
            }
        }
        CPA_COMMIT();

        const uint32_t sb = sbase + (uint32_t)(st * 40960);
        #pragma unroll
        for (int ks = 0; ks < 2; ks++) {
            const uint32_t cb = (uint32_t)(ks * 16) * 2 + acb_col * 2;

            uint32_t ah[4][4], bh[2][4];
            #pragma unroll
            for (int i = 0; i < 4; i++)
                ldm4(sb + (uint32_t)((wm + i * 16) + acb_row) * 80u + cb, ah[i]);
            #pragma unroll
            for (int nb = 0; nb < 2; nb++)
                ldm4(sb + 20480u + (uint32_t)((wn + nb * 16) + acb_row) * 80u + cb, bh[nb]);

            #pragma unroll
            for (int i = 0; i < 4; i++)
                #pragma unroll
                for (int nb = 0; nb < 2; nb++) {
                    mma16816(d[i][2*nb],     ah[i], bh[nb][0], bh[nb][2]);
                    mma16816(d[i][2*nb + 1], ah[i], bh[nb][1], bh[nb][3]);
                }
            {
                uint32_t bl[2][4];
                #pragma unroll
                for (int nb = 0; nb < 2; nb++)
                    ldm4(sb + 30720u + (uint32_t)((wn + nb * 16) + acb_row) * 80u + cb, bl[nb]);
                #pragma unroll
                for (int i = 0; i < 4; i++)
                    #pragma unroll
                    for (int nb = 0; nb < 2; nb++) {
                        mma16816(d[i][2*nb],     ah[i], bl[nb][0], bl[nb][2]);
                        mma16816(d[i][2*nb + 1], ah[i], bl[nb][1], bl[nb][3]);
                    }
            }
            {
                uint32_t al[4][4];
                #pragma unroll
                for (int i = 0; i < 4; i++)
                    ldm4(sb + 10240u + (uint32_t)((wm + i * 16) + acb_row) * 80u + cb, al[i]);
                #pragma unroll
                for (int i = 0; i < 4; i++)
                    #pragma unroll
                    for (int nb = 0; nb < 2; nb++) {
                        mma16816(d[i][2*nb],     al[i], bh[nb][0], bh[nb][2]);
                        mma16816(d[i][2*nb + 1], al[i], bh[nb][1], bh[nb][3]);
                    }
            }
        }
        CPA_WAIT0();
        __syncthreads();
    }

    const int er = bm + wm + (lane >> 2);
    const int ec = bn + wn + (lane & 3) * 2;
    #pragma unroll
    for (int i = 0; i < 4; i++) {
        const int r1 = er + i * 16;
        #pragma unroll
        for (int jj = 0; jj < 4; jj++) {
            const int c = ec + jj * 8;
            size_t o0 = (size_t)r1 * GK + c;
            size_t o1 = (size_t)(r1 + 8) * GK + c;
            if (OH) {
                uint32_t hu, lu;
                pack_split(d[i][jj][0], d[i][jj][1], hu, lu);
                *(uint32_t*)(OH + o0) = hu;
                *(uint32_t*)(OL + o0) = lu;
                pack_split(d[i][jj][2], d[i][jj][3], hu, lu);
                *(uint32_t*)(OH + o1) = hu;
                *(uint32_t*)(OL + o1) = lu;
            } else {
                float2 v0 = make_float2(d[i][jj][0], d[i][jj][1]);
                float2 v1 = make_float2(d[i][jj][2], d[i][jj][3]);
                if (resid) {
                    float2 q0 = *(const float2*)(resid + o0);
                    float2 q1 = *(const float2*)(resid + o1);
                    v0.x += q0.x; v0.y += q0.y;
                    v1.x += q1.x; v1.y += q1.y;
                }
                *(float2*)(C + o0) = v0;
                *(float2*)(C + o1) = v1;
            }
        }
    }
}

// ---------------------------------------------------------------------------
// fp32 -> bf16 hi/lo split
// ---------------------------------------------------------------------------
__global__ __launch_bounds__(256) void conv_act(
    const float* __restrict__ X, __nv_bfloat16* __restrict__ H,
    __nv_bfloat16* __restrict__ L)
{
    int i = blockIdx.x * 256 + threadIdx.x;
    float4 v = ((const float4*)X)[i];
    float vv[4] = {v.x, v.y, v.z, v.w};
    __nv_bfloat16 h[4], l[4];
    #pragma unroll
    for (int j = 0; j < 4; j++) {
        h[j] = __float2bfloat16(vv[j]);
        l[j] = __float2bfloat16(vv[j] - __bfloat162float(h[j]));
    }
    uint64_t hp, lp;
    memcpy(&hp, h, 8); memcpy(&lp, l, 8);
    ((uint64_t*)H)[i] = hp;
    ((uint64_t*)L)[i] = lp;
}

// ---------------------------------------------------------------------------
// W [K][N] fp32 -> W^T hi/lo bf16 [N][K]  (clock canary: DRAM-bound ~5us)
// ---------------------------------------------------------------------------
__global__ __launch_bounds__(256) void conv_wt(
    const float* __restrict__ W, __nv_bfloat16* __restrict__ TH,
    __nv_bfloat16* __restrict__ TL)
{
    __shared__ float t[32][33];
    const int bxn = blockIdx.x * 32;
    const int byk = blockIdx.y * 32;
    const int tx = threadIdx.x & 31;
    const int ty4 = (threadIdx.x >> 5) * 4;

    #pragma unroll
    for (int j = 0; j < 4; j++)
        t[ty4 + j][tx] = W[(size_t)(byk + ty4 + j) * Dd + bxn + tx];
    __syncthreads();

    #pragma unroll
    for (int j = 0; j < 4; j++) {
        float x = t[tx][ty4 + j];
        __nv_bfloat16 h = __float2bfloat16(x);
        __nv_bfloat16 l = __float2bfloat16(x - __bfloat162float(h));
        size_t o = (size_t)(bxn + ty4 + j) * Dd + byk + tx;
        TH[o] = h;
        TL[o] = l;
    }
}

// ---------------------------------------------------------------------------
// HMMA flash attention (causal), split-bf16 Q/K/P/V.
// Q (hi+lo) persistent in SMEM; K/V double-buffer above. ~110 regs, 2 CTAs/SM.
// ---------------------------------------------------------------------------
#define AT_ROWB   144
#define AT_TILE_B (64 * AT_ROWB)          // 9216
#define AT_STAGE_B (4 * AT_TILE_B)        // 36864
#define AT_Q_B    36864
#define ATTN2_SMEM (AT_Q_B + 2 * AT_STAGE_B)   // 110592
#define CS 0.18033688011112042f           // log2(e)/8

__global__ __launch_bounds__(256, 2) void attn_tc(
    const __nv_bfloat16* __restrict__ Qh, const __nv_bfloat16* __restrict__ Ql,
    const __nv_bfloat16* __restrict__ Kh, const __nv_bfloat16* __restrict__ Kl,
    const __nv_bfloat16* __restrict__ Vh, const __nv_bfloat16* __restrict__ Vl,
    __nv_bfloat16* __restrict__ Oh, __nv_bfloat16* __restrict__ Ol)
{
    extern __shared__ char smc[];
    const int tid = threadIdx.x;
    const int lane = tid & 31;
    const int w = tid >> 5;
    const int bx = blockIdx.x, h = blockIdx.y, b = blockIdx.z;
    const int q0 = bx * 128;
    const uint32_t sb = smem_u32(smc);
    const uint32_t kvb = sb + AT_Q_B;
    const size_t headoff = (size_t)b * Ss * Dd + (size_t)h * HDd;

    // ---- Q tiles -> persistent SMEM (hi @0, lo @18432)
    {
        const __nv_bfloat16* gq  = Qh + headoff + (size_t)q0 * Dd;
        const __nv_bfloat16* gql = Ql + headoff + (size_t)q0 * Dd;
        #pragma unroll
        for (int it = 0; it < 4; it++) {
            int f = tid + it * 256;
            int r = f >> 3, ch = f & 7;
            uint32_t so = sb + (uint32_t)(r * AT_ROWB + ch * 16);
            size_t go = (size_t)r * Dd + ch * 8;
            cpa16(so, gq + go);
            cpa16(so + 18432u, gql + go);
        }
        CPA_COMMIT();
        CPA_WAIT0();
    }
    __syncthreads();

    const uint32_t qlb = sb + (uint32_t)((16 * w + (lane & 15)) * AT_ROWB
                                         + (lane >> 4) * 16);

    float oacc[8][4];
    #pragma unroll
    for (int i = 0; i < 8; i++)
        #pragma unroll
        for (int e = 0; e < 4; e++) oacc[i][e] = 0.f;
    float m0 = -1e30f, m1 = -1e30f, l0 = 0.f, l1 = 0.f;
    const int r0g = q0 + 16 * w + (lane >> 2);
    const int r1g = r0g + 8;

    const int nkt = 2 * bx + 2;
    const __nv_bfloat16 *gkh = Kh + headoff, *gkl = Kl + headoff;
    const __nv_bfloat16 *gvh = Vh + headoff, *gvl = Vl + headoff;

    #pragma unroll
    for (int it = 0; it < 2; it++) {
        int f = tid + it * 256;
        int r = f >> 3, ch = f & 7;
        uint32_t so = kvb + (uint32_t)(r * AT_ROWB + ch * 16);
        size_t go = (size_t)r * Dd + ch * 8;
        cpa16(so,                  gkh + go);
        cpa16(so + AT_TILE_B,      gkl + go);
        cpa16(so + 2 * AT_TILE_B,  gvh + go);
        cpa16(so + 3 * AT_TILE_B,  gvl + go);
    }
    CPA_COMMIT();

    for (int kt = 0; kt < nkt; kt++) {
        __syncthreads();
        if (kt + 1 < nkt) {
            const uint32_t st2 = kvb + (uint32_t)(((kt + 1) & 1) * AT_STAGE_B);
            const size_t kb = (size_t)(kt + 1) * 64 * Dd;
            #pragma unroll
            for (int it = 0; it < 2; it++) {
                int f = tid + it * 256;
                int r = f >> 3, ch = f & 7;
                uint32_t so = st2 + (uint32_t)(r * AT_ROWB + ch * 16);
                size_t go = kb + (size_t)r * Dd + ch * 8;
                cpa16(so,                 gkh + go);
                cpa16(so + AT_TILE_B,     gkl + go);
                cpa16(so + 2 * AT_TILE_B, gvh + go);
                cpa16(so + 3 * AT_TILE_B, gvl + go);
            }
            CPA_COMMIT();
            CPA_WAIT1();
        } else {
            CPA_WAIT0();
        }
        __syncthreads();

        const int k0 = kt * 64;
        const bool active = (k0 <= q0 + 16 * w + 15);
        if (active) {
            const uint32_t stg = kvb + (uint32_t)((kt & 1) * AT_STAGE_B);
            float sacc[8][4];
            #pragma unroll
            for (int i = 0; i < 8; i++)
                #pragma unroll
                for (int e = 0; e < 4; e++) sacc[i][e] = 0.f;

            const uint32_t lb = stg + (uint32_t)((lane & 15) * AT_ROWB
                                                 + (lane >> 4) * 16);
            #pragma unroll
            for (int c = 0; c < 4; c++) {
                uint32_t qh4[4], ql4[4];
                ldm4(qlb + (uint32_t)(c * 32), qh4);
                ldm4(qlb + 18432u + (uint32_t)(c * 32), ql4);
                #pragma unroll
                for (int g = 0; g < 4; g++) {
                    uint32_t kh4[4], kl4[4];
                    uint32_t a = lb + (uint32_t)(g * 16 * AT_ROWB + c * 32);
                    ldm4(a, kh4);
                    ldm4(a + AT_TILE_B, kl4);
                    mma16816(sacc[2*g],   qh4, kh4[0], kh4[2]);
                    mma16816(sacc[2*g+1], qh4, kh4[1], kh4[3]);
                    mma16816(sacc[2*g],   qh4, kl4[0], kl4[2]);
                    mma16816(sacc[2*g+1], qh4, kl4[1], kl4[3]);
                    mma16816(sacc[2*g],   ql4, kh4[0], kh4[2]);
                    mma16816(sacc[2*g+1], ql4, kh4[1], kh4[3]);
                }
            }

            if (k0 + 63 > q0 + 16 * w) {
                #pragma unroll
                for (int nb = 0; nb < 8; nb++) {
                    int col = k0 + nb * 8 + (lane & 3) * 2;
                    if (col     > r0g) sacc[nb][0] = -1e30f;
                    if (col + 1 > r0g) sacc[nb][1] = -1e30f;
                    if (col     > r1g) sacc[nb][2] = -1e30f;
                    if (col + 1 > r1g) sacc[nb][3] = -1e30f;
                }
            }

            float mx0 = -1e30f, mx1 = -1e30f;
            #pragma unroll
            for (int nb = 0; nb < 8; nb++) {
                mx0 = fmaxf(mx0, fmaxf(sacc[nb][0], sacc[nb][1]));
                mx1 = fmaxf(mx1, fmaxf(sacc[nb][2], sacc[nb][3]));
            }
            mx0 = fmaxf(mx0, __shfl_xor_sync(0xffffffffu, mx0, 1));
            mx0 = fmaxf(mx0, __shfl_xor_sync(0xffffffffu, mx0, 2));
            mx1 = fmaxf(mx1, __shfl_xor_sync(0xffffffffu, mx1, 1));
            mx1 = fmaxf(mx1, __shfl_xor_sync(0xffffffffu, mx1, 2));
            const float nm0 = fmaxf(m0, mx0), nm1 = fmaxf(m1, mx1);
            const float a0 = exp2f((m0 - nm0) * CS);
            const float a1 = exp2f((m1 - nm1) * CS);
            m0 = nm0; m1 = nm1;
            const float c0 = nm0 * CS, c1 = nm1 * CS;
            float s0 = 0.f, s1 = 0.f;
            #pragma unroll
            for (int nb = 0; nb < 8; nb++) {
                float p0 = exp2f(fmaf(sacc[nb][0], CS, -c0));
                float p1 = exp2f(fmaf(sacc[nb][1], CS, -c0));
                float p2 = exp2f(fmaf(sacc[nb][2], CS, -c1));
                float p3 = exp2f(fmaf(sacc[nb][3], CS, -c1));
                sacc[nb][0] = p0; sacc[nb][1] = p1;
                sacc[nb][2] = p2; sacc[nb][3] = p3;
                s0 += p0 + p1;
                s1 += p2 + p3;
            }
            s0 += __shfl_xor_sync(0xffffffffu, s0, 1);
            s0 += __shfl_xor_sync(0xffffffffu, s0, 2);
            s1 += __shfl_xor_sync(0xffffffffu, s1, 1);
            s1 += __shfl_xor_sync(0xffffffffu, s1, 2);
            l0 = l0 * a0 + s0;
            l1 = l1 * a1 + s1;
            #pragma unroll
            for (int i = 0; i < 8; i++) {
                oacc[i][0] *= a0; oacc[i][1] *= a0;
                oacc[i][2] *= a1; oacc[i][3] *= a1;
            }

            #pragma unroll
            for (int j = 0; j < 4; j++) {
                uint32_t pa[4], pl[4];
                pack_split(sacc[2*j][0],   sacc[2*j][1],   pa[0], pl[0]);
                pack_split(sacc[2*j][2],   sacc[2*j][3],   pa[1], pl[1]);
                pack_split(sacc[2*j+1][0], sacc[2*j+1][1], pa[2], pl[2]);
                pack_split(sacc[2*j+1][2], sacc[2*j+1][3], pa[3], pl[3]);
                const uint32_t vb = stg + 2 * AT_TILE_B
                    + (uint32_t)((16 * j + (lane & 15)) * AT_ROWB + (lane >> 4) * 16);
                #pragma unroll
                for (int dp = 0; dp < 4; dp++) {
                    uint32_t vh4[4], vl4[4];
                    ldm4t(vb + (uint32_t)(dp * 32), vh4);
                    ldm4t(vb + AT_TILE_B + (uint32_t)(dp * 32), vl4);
                    mma16816(oacc[2*dp],   pa, vh4[0], vh4[1]);
                    mma16816(oacc[2*dp+1], pa, vh4[2], vh4[3]);
                    mma16816(oacc[2*dp],   pa, vl4[0], vl4[1]);
                    mma16816(oacc[2*dp+1], pa, vl4[2], vl4[3]);
                    mma16816(oacc[2*dp],   pl, vh4[0], vh4[1]);
                    mma16816(oacc[2*dp+1], pl, vh4[2], vh4[3]);
                }
            }
        }
    }

    const float i0 = 1.f / l0, i1 = 1.f / l1;
    const size_t ro0 = (size_t)b * Ss * Dd + (size_t)r0g * Dd + (size_t)h * HDd;
    const size_t ro1 = ro0 + 8 * Dd;
    #pragma unroll
    for (int nb = 0; nb < 8; nb++) {
        const int dcol = nb * 8 + (lane & 3) * 2;
        uint32_t hu, lu;
        pack_split(oacc[nb][0] * i0, oacc[nb][1] * i0, hu, lu);
        *(uint32_t*)(Oh + ro0 + dcol) = hu;
        *(uint32_t*)(Ol + ro0 + dcol) = lu;
        pack_split(oacc[nb][2] * i1, oacc[nb][3] * i1, hu, lu);
        *(uint32_t*)(Oh + ro1 + dcol) = hu;
        *(uint32_t*)(Ol + ro1 + dcol) = lu;
    }
}

// ---------------------------------------------------------------------------
// LayerNorm over last dim (1024)
// ---------------------------------------------------------------------------
__global__ __launch_bounds__(256) void ln_kernel(
    const float* __restrict__ X, const float* __restrict__ gamma,
    const float* __restrict__ beta, float* __restrict__ Y)
{
    const int row = blockIdx.x;
    const int t = threadIdx.x;
    const float4 v = ((const float4*)(X + (size_t)row * Dd))[t];

    float s  = v.x + v.y + v.z + v.w;
    float ss = v.x * v.x + v.y * v.y + v.z * v.z + v.w * v.w;
    #pragma unroll
    for (int o = 16; o > 0; o >>= 1) {
        s  += __shfl_xor_sync(0xffffffffu, s,  o);
        ss += __shfl_xor_sync(0xffffffffu, ss, o);
    }
    __shared__ float sh[8][2];
    if ((t & 31) == 0) { sh[t >> 5][0] = s; sh[t >> 5][1] = ss; }
    __syncthreads();
    float ts = 0.f, tss = 0.f;
    #pragma unroll
    for (int i = 0; i < 8; i++) { ts += sh[i][0]; tss += sh[i][1]; }

    const float mu  = ts * (1.0f / Dd);
    const float var = tss * (1.0f / Dd) - mu * mu;
    const float inv = rsqrtf(var + LN_EPS);

    const float4 gg = ((const float4*)gamma)[t];
    const float4 bb = ((const float4*)beta)[t];
    float4 y;
    y.x = (v.x - mu) * inv * gg.x + bb.x;
    y.y = (v.y - mu) * inv * gg.y + bb.y;
    y.z = (v.z - mu) * inv * gg.z + bb.z;
    y.w = (v.w - mu) * inv * gg.w + bb.w;
    ((float4*)(Y + (size_t)row * Dd))[t] = y;
}

// ---------------------------------------------------------------------------
// Launch. Inputs: q, k, v, wq, wk, wv, wo, gamma, beta, mask (causal; unused).
// ---------------------------------------------------------------------------
extern "C" void kernel_launch(void* const* d_in, const int* in_sizes, int n_in,
                              void* d_out, int out_size)
{
    const float* q     = (const float*)d_in[0];
    const float* k     = (const float*)d_in[1];
    const float* v     = (const float*)d_in[2];
    const float* wq    = (const float*)d_in[3];
    const float* wk    = (const float*)d_in[4];
    const float* wv    = (const float*)d_in[5];
    const float* wo    = (const float*)d_in[6];
    const float* gamma = (const float*)d_in[7];
    const float* beta  = (const float*)d_in[8];
    float* out = (float*)d_out;

    float* gtmp;
    __nv_bfloat16 *gah, *gal, *gwh, *gwl;
    __nv_bfloat16 *gqh, *gql, *gkh, *gkl, *gvh, *gvl, *goh, *gol;
    cudaGetSymbolAddress((void**)&gtmp, g_tmp);
    cudaGetSymbolAddress((void**)&gah,  g_ah);
    cudaGetSymbolAddress((void**)&gal,  g_al);
    cudaGetSymbolAddress((void**)&gwh,  g_wh);
    cudaGetSymbolAddress((void**)&gwl,  g_wl);
    cudaGetSymbolAddress((void**)&gqh,  g_qh);
    cudaGetSymbolAddress((void**)&gql,  g_ql);
    cudaGetSymbolAddress((void**)&gkh,  g_kh);
    cudaGetSymbolAddress((void**)&gkl,  g_kl);
    cudaGetSymbolAddress((void**)&gvh,  g_vh);
    cudaGetSymbolAddress((void**)&gvl,  g_vl);
    cudaGetSymbolAddress((void**)&goh,  g_oh);
    cudaGetSymbolAddress((void**)&gol,  g_ol);

    cudaFuncSetAttribute(gemm_tc,
                         cudaFuncAttributeMaxDynamicSharedMemorySize, GEMM_SMEM);
    cudaFuncSetAttribute(attn_tc,
                         cudaFuncAttributeMaxDynamicSharedMemorySize, ATTN2_SMEM);

    const dim3 blk256(256);
    const dim3 gconv(MS * Dd / 4 / 256);
    const dim3 gwt(Dd / 32, Dd / 32);
    const dim3 ggemm(Dd / 128, MS / 128);     // (8, 32)

    // Q projection -> split
    conv_wt<<<gwt, blk256>>>(wq, gwh, gwl);
    conv_act<<<gconv, blk256>>>(q, gah, gal);
    gemm_tc<<<ggemm, blk256, GEMM_SMEM>>>(gah, gal, gwh, gwl, nullptr, nullptr, gqh, gql);
    // K projection -> split
    conv_wt<<<gwt, blk256>>>(wk, gwh, gwl);
    conv_act<<<gconv, blk256>>>(k, gah, gal);
    gemm_tc<<<ggemm, blk256, GEMM_SMEM>>>(gah, gal, gwh, gwl, nullptr, nullptr, gkh, gkl);
    // V projection -> split
    conv_wt<<<gwt, blk256>>>(wv, gwh, gwl);
    conv_act<<<gconv, blk256>>>(v, gah, gal);
    gemm_tc<<<ggemm, blk256, GEMM_SMEM>>>(gah, gal, gwh, gwl, nullptr, nullptr, gvh, gvl);

    // flash attention (tensor cores) -> split output
    dim3 ga(Ss / 128, Hh, Bb);                // (16, 16, 2)
    attn_tc<<<ga, blk256, ATTN2_SMEM>>>(gqh, gql, gkh, gkl, gvh, gvl, goh, gol);

    // output projection + residual (fp32 out)
    conv_wt<<<gwt, blk256>>>(wo, gwh, gwl);
    gemm_tc<<<ggemm, blk256, GEMM_SMEM>>>(goh, gol, gwh, gwl, q, gtmp, nullptr, nullptr);

    // LayerNorm
    ln_kernel<<<MS, blk256>>>(gtmp, gamma, beta, out);
}

// round 10
// speedup vs baseline: 1.0344x; 1.0064x over previous
#include <cuda_runtime.h>
#include <cuda_bf16.h>
#include <cstdint>

// Problem constants
#define Bb  2
#define Ss  2048
#define Dd  1024
#define Hh  16
#define HDd 64
#define MS  (Bb*Ss)          // 4096 rows
#define LN_EPS 1e-5f
#define GK 1024
#define PSZ ((size_t)MS * Dd)
#define WSZ ((size_t)Dd * Dd)

// ---------------------------------------------------------------------------
// Scratch (device globals)
// ---------------------------------------------------------------------------
__device__ float g_tmp[MS*Dd];                 // pre-LN
__device__ __nv_bfloat16 g_xh[3*MS*Dd];        // staged inputs hi (q,k,v planes)
__device__ __nv_bfloat16 g_xl[3*MS*Dd];
__device__ __nv_bfloat16 g_wth[4*Dd*Dd];       // W^T hi [N][K] (wq,wk,wv,wo)
__device__ __nv_bfloat16 g_wtl[4*Dd*Dd];
__device__ __nv_bfloat16 g_ph[3*MS*Dd];        // projections hi (Q,K,V planes)
__device__ __nv_bfloat16 g_pl[3*MS*Dd];
__device__ __nv_bfloat16 g_oh[MS*Dd], g_ol[MS*Dd];

// ---------------------------------------------------------------------------
// Helpers
// ---------------------------------------------------------------------------
__device__ __forceinline__ uint32_t smem_u32(const void* p) {
    uint32_t a;
    asm("{ .reg .u64 t; cvta.to.shared.u64 t, %1; cvt.u32.u64 %0, t; }"
        : "=r"(a) : "l"(p));
    return a;
}
__device__ __forceinline__ void cpa16(uint32_t s, const void* g) {
    asm volatile("cp.async.cg.shared.global [%0], [%1], 16;" :: "r"(s), "l"(g));
}
#define CPA_COMMIT() asm volatile("cp.async.commit_group;" ::: "memory")
#define CPA_WAIT0()  asm volatile("cp.async.wait_group 0;" ::: "memory")
#define CPA_WAIT1()  asm volatile("cp.async.wait_group 1;" ::: "memory")

__device__ __forceinline__ void ldm4(uint32_t a, uint32_t r[4]) {
    asm volatile("ldmatrix.sync.aligned.m8n8.x4.shared.b16 {%0,%1,%2,%3}, [%4];"
                 : "=r"(r[0]), "=r"(r[1]), "=r"(r[2]), "=r"(r[3]) : "r"(a));
}
__device__ __forceinline__ void ldm4t(uint32_t a, uint32_t r[4]) {
    asm volatile("ldmatrix.sync.aligned.m8n8.x4.trans.shared.b16 {%0,%1,%2,%3}, [%4];"
                 : "=r"(r[0]), "=r"(r[1]), "=r"(r[2]), "=r"(r[3]) : "r"(a));
}
__device__ __forceinline__ void mma16816(float d[4], const uint32_t a[4],
                                         uint32_t b0, uint32_t b1) {
    asm volatile(
        "mma.sync.aligned.m16n8k16.row.col.f32.bf16.bf16.f32 "
        "{%0,%1,%2,%3}, {%4,%5,%6,%7}, {%8,%9}, {%0,%1,%2,%3};"
        : "+f"(d[0]), "+f"(d[1]), "+f"(d[2]), "+f"(d[3])
        : "r"(a[0]), "r"(a[1]), "r"(a[2]), "r"(a[3]), "r"(b0), "r"(b1));
}
__device__ __forceinline__ void pack_split(float x, float y,
                                           uint32_t& hi, uint32_t& lo) {
    __nv_bfloat16 hx = __float2bfloat16(x), hy = __float2bfloat16(y);
    __nv_bfloat16 lx = __float2bfloat16(x - __bfloat162float(hx));
    __nv_bfloat16 ly = __float2bfloat16(y - __bfloat162float(hy));
    hi = (uint32_t)__bfloat16_as_ushort(hx) | ((uint32_t)__bfloat16_as_ushort(hy) << 16);
    lo = (uint32_t)__bfloat16_as_ushort(lx) | ((uint32_t)__bfloat16_as_ushort(ly) << 16);
}

#define GEMM_SMEM 81920

// ---------------------------------------------------------------------------
// Split-bf16 HMMA GEMM — R9 exact: 256 threads, 128x128 CTA tile, 64x32 warp
// tile, 64 fp32 accums/thread, __launch_bounds__(256,2) -> 2 CTAs/SM.
// ---------------------------------------------------------------------------
__global__ __launch_bounds__(256, 2)
void gemm_tc(const __nv_bfloat16* __restrict__ Ah, const __nv_bfloat16* __restrict__ Al,
             const __nv_bfloat16* __restrict__ Wh, const __nv_bfloat16* __restrict__ Wl,
             const float* __restrict__ resid, float* __restrict__ C,
             __nv_bfloat16* __restrict__ OH, __nv_bfloat16* __restrict__ OL)
{
    extern __shared__ __nv_bfloat16 S[];
    const int tid  = threadIdx.x;
    const int lane = tid & 31;
    const int wid  = tid >> 5;            // 0..7
    const int bm = blockIdx.y * 128;
    const int bn = blockIdx.x * 128;
    const int wm = (wid & 1) * 64;
    const int wn = (wid >> 1) * 32;

    const __nv_bfloat16* gA  = Ah + (size_t)bm * GK;
    const __nv_bfloat16* gAl = Al + (size_t)bm * GK;
    const __nv_bfloat16* gB  = Wh + (size_t)bn * GK;
    const __nv_bfloat16* gBl = Wl + (size_t)bn * GK;

    const uint32_t sbase = smem_u32(S);

    float d[4][4][4];
    #pragma unroll
    for (int i = 0; i < 4; i++)
        #pragma unroll
        for (int j = 0; j < 4; j++)
            #pragma unroll
            for (int e = 0; e < 4; e++) d[i][j][e] = 0.f;

    const uint32_t acb_row = (uint32_t)(lane & 15);
    const uint32_t acb_col = (uint32_t)((lane >> 4) * 8);

    {
        #pragma unroll
        for (int it = 0; it < 2; it++) {
            int f = tid + it * 256;
            int r = f >> 2;
            int u = f & 3;
            uint32_t so = sbase + (uint32_t)(r * 40 + u * 8) * 2;
            size_t go = (size_t)r * GK + u * 8;
            cpa16(so,          gA  + go);
            cpa16(so + 10240u, gAl + go);
            cpa16(so + 20480u, gB  + go);
            cpa16(so + 30720u, gBl + go);
        }
        CPA_COMMIT();
        CPA_WAIT0();
        __syncthreads();
    }

    for (int ic = 0; ic < 32; ic++) {
        const int st = ic & 1;
        if (ic + 1 < 32) {
            const int k0 = (ic + 1) * 32;
            const uint32_t sb2 = sbase + (uint32_t)((st ^ 1) * 40960);
            #pragma unroll
            for (int it = 0; it < 2; it++) {
                int f = tid + it * 256;
                int r = f >> 2;
                int u = f & 3;
                uint32_t so = sb2 + (uint32_t)(r * 40 + u * 8) * 2;
                size_t go = (size_t)r * GK + k0 + u * 8;
                cpa16(so,          gA  + go);
                cpa16(so + 10240u, gAl + go);
                cpa16(so + 20480u, gB  + go);
                cpa16(so + 30720u, gBl + go);
            }
        }
        CPA_COMMIT();

        const uint32_t sb = sbase + (uint32_t)(st * 40960);
        #pragma unroll
        for (int ks = 0; ks < 2; ks++) {
            const uint32_t cb = (uint32_t)(ks * 16) * 2 + acb_col * 2;

            uint32_t ah[4][4], bh[2][4];
            #pragma unroll
            for (int i = 0; i < 4; i++)
                ldm4(sb + (uint32_t)((wm + i * 16) + acb_row) * 80u + cb, ah[i]);
            #pragma unroll
            for (int nb = 0; nb < 2; nb++)
                ldm4(sb + 20480u + (uint32_t)((wn + nb * 16) + acb_row) * 80u + cb, bh[nb]);

            #pragma unroll
            for (int i = 0; i < 4; i++)
                #pragma unroll
                for (int nb = 0; nb < 2; nb++) {
                    mma16816(d[i][2*nb],     ah[i], bh[nb][0], bh[nb][2]);
                    mma16816(d[i][2*nb + 1], ah[i], bh[nb][1], bh[nb][3]);
                }
            {
                uint32_t bl[2][4];
                #pragma unroll
                for (int nb = 0; nb < 2; nb++)
                    ldm4(sb + 30720u + (uint32_t)((wn + nb * 16) + acb_row) * 80u + cb, bl[nb]);
                #pragma unroll
                for (int i = 0; i < 4; i++)
                    #pragma unroll
                    for (int nb = 0; nb < 2; nb++) {
                        mma16816(d[i][2*nb],     ah[i], bl[nb][0], bl[nb][2]);
                        mma16816(d[i][2*nb + 1], ah[i], bl[nb][1], bl[nb][3]);
                    }
            }
            {
                uint32_t al[4][4];
                #pragma unroll
                for (int i = 0; i < 4; i++)
                    ldm4(sb + 10240u + (uint32_t)((wm + i * 16) + acb_row) * 80u + cb, al[i]);
                #pragma unroll
                for (int i = 0; i < 4; i++)
                    #pragma unroll
                    for (int nb = 0; nb < 2; nb++) {
                        mma16816(d[i][2*nb],     al[i], bh[nb][0], bh[nb][2]);
                        mma16816(d[i][2*nb + 1], al[i], bh[nb][1], bh[nb][3]);
                    }
            }
        }
        CPA_WAIT0();
        __syncthreads();
    }

    const int er = bm + wm + (lane >> 2);
    const int ec = bn + wn + (lane & 3) * 2;
    #pragma unroll
    for (int i = 0; i < 4; i++) {
        const int r1 = er + i * 16;
        #pragma unroll
        for (int jj = 0; jj < 4; jj++) {
            const int c = ec + jj * 8;
            size_t o0 = (size_t)r1 * GK + c;
            size_t o1 = (size_t)(r1 + 8) * GK + c;
            if (OH) {
                uint32_t hu, lu;
                pack_split(d[i][jj][0], d[i][jj][1], hu, lu);
                *(uint32_t*)(OH + o0) = hu;
                *(uint32_t*)(OL + o0) = lu;
                pack_split(d[i][jj][2], d[i][jj][3], hu, lu);
                *(uint32_t*)(OH + o1) = hu;
                *(uint32_t*)(OL + o1) = lu;
            } else {
                float2 v0 = make_float2(d[i][jj][0], d[i][jj][1]);
                float2 v1 = make_float2(d[i][jj][2], d[i][jj][3]);
                if (resid) {
                    float2 q0 = *(const float2*)(resid + o0);
                    float2 q1 = *(const float2*)(resid + o1);
                    v0.x += q0.x; v0.y += q0.y;
                    v1.x += q1.x; v1.y += q1.y;
                }
                *(float2*)(C + o0) = v0;
                *(float2*)(C + o1) = v1;
            }
        }
    }
}

// ---------------------------------------------------------------------------
// fp32 -> bf16 hi/lo split; grid.z selects source (q,k,v) -> plane z
// ---------------------------------------------------------------------------
__global__ __launch_bounds__(256) void conv_act_all(
    const float* __restrict__ X0, const float* __restrict__ X1,
    const float* __restrict__ X2,
    __nv_bfloat16* __restrict__ H, __nv_bfloat16* __restrict__ L)
{
    const int z = blockIdx.z;
    const float* X = (z == 0) ? X0 : (z == 1) ? X1 : X2;
    size_t i = (size_t)blockIdx.x * 256 + threadIdx.x;
    float4 v = ((const float4*)X)[i];
    float vv[4] = {v.x, v.y, v.z, v.w};
    __nv_bfloat16 h[4], l[4];
    #pragma unroll
    for (int j = 0; j < 4; j++) {
        h[j] = __float2bfloat16(vv[j]);
        l[j] = __float2bfloat16(vv[j] - __bfloat162float(h[j]));
    }
    uint64_t hp, lp;
    memcpy(&hp, h, 8); memcpy(&lp, l, 8);
    const size_t zo4 = (size_t)z * (PSZ / 4);
    ((uint64_t*)H)[zo4 + i] = hp;
    ((uint64_t*)L)[zo4 + i] = lp;
}

// ---------------------------------------------------------------------------
// W [K][N] fp32 -> W^T hi/lo bf16 [N][K]; grid.z selects (wq,wk,wv,wo)
// ---------------------------------------------------------------------------
__global__ __launch_bounds__(256) void conv_wt_all(
    const float* __restrict__ W0, const float* __restrict__ W1,
    const float* __restrict__ W2, const float* __restrict__ W3,
    __nv_bfloat16* __restrict__ TH, __nv_bfloat16* __restrict__ TL)
{
    __shared__ float t[32][33];
    const int z = blockIdx.z;
    const float* W = (z == 0) ? W0 : (z == 1) ? W1 : (z == 2) ? W2 : W3;
    const size_t zw = (size_t)z * WSZ;
    const int bxn = blockIdx.x * 32;
    const int byk = blockIdx.y * 32;
    const int tx = threadIdx.x & 31;
    const int ty4 = (threadIdx.x >> 5) * 4;

    #pragma unroll
    for (int j = 0; j < 4; j++)
        t[ty4 + j][tx] = W[(size_t)(byk + ty4 + j) * Dd + bxn + tx];
    __syncthreads();

    #pragma unroll
    for (int j = 0; j < 4; j++) {
        float x = t[tx][ty4 + j];
        __nv_bfloat16 h = __float2bfloat16(x);
        __nv_bfloat16 l = __float2bfloat16(x - __bfloat162float(h));
        size_t o = zw + (size_t)(bxn + ty4 + j) * Dd + byk + tx;
        TH[o] = h;
        TL[o] = l;
    }
}

// ---------------------------------------------------------------------------
// HMMA flash attention — R9 exact: smem-resident Q, 2 CTAs/SM.
// ---------------------------------------------------------------------------
#define AT_ROWB   144
#define AT_TILE_B (64 * AT_ROWB)          // 9216
#define AT_STAGE_B (4 * AT_TILE_B)        // 36864
#define AT_Q_B    36864
#define ATTN2_SMEM (AT_Q_B + 2 * AT_STAGE_B)   // 110592
#define CS 0.18033688011112042f           // log2(e)/8

__global__ __launch_bounds__(256, 2) void attn_tc(
    const __nv_bfloat16* __restrict__ Qh, const __nv_bfloat16* __restrict__ Ql,
    const __nv_bfloat16* __restrict__ Kh, const __nv_bfloat16* __restrict__ Kl,
    const __nv_bfloat16* __restrict__ Vh, const __nv_bfloat16* __restrict__ Vl,
    __nv_bfloat16* __restrict__ Oh, __nv_bfloat16* __restrict__ Ol)
{
    extern __shared__ char smc[];
    const int tid = threadIdx.x;
    const int lane = tid & 31;
    const int w = tid >> 5;
    const int bx = blockIdx.x, h = blockIdx.y, b = blockIdx.z;
    const int q0 = bx * 128;
    const uint32_t sb = smem_u32(smc);
    const uint32_t kvb = sb + AT_Q_B;
    const size_t headoff = (size_t)b * Ss * Dd + (size_t)h * HDd;

    {
        const __nv_bfloat16* gq  = Qh + headoff + (size_t)q0 * Dd;
        const __nv_bfloat16* gql = Ql + headoff + (size_t)q0 * Dd;
        #pragma unroll
        for (int it = 0; it < 4; it++) {
            int f = tid + it * 256;
            int r = f >> 3, ch = f & 7;
            uint32_t so = sb + (uint32_t)(r * AT_ROWB + ch * 16);
            size_t go = (size_t)r * Dd + ch * 8;
            cpa16(so, gq + go);
            cpa16(so + 18432u, gql + go);
        }
        CPA_COMMIT();
        CPA_WAIT0();
    }
    __syncthreads();

    const uint32_t qlb = sb + (uint32_t)((16 * w + (lane & 15)) * AT_ROWB
                                         + (lane >> 4) * 16);

    float oacc[8][4];
    #pragma unroll
    for (int i = 0; i < 8; i++)
        #pragma unroll
        for (int e = 0; e < 4; e++) oacc[i][e] = 0.f;
    float m0 = -1e30f, m1 = -1e30f, l0 = 0.f, l1 = 0.f;
    const int r0g = q0 + 16 * w + (lane >> 2);
    const int r1g = r0g + 8;

    const int nkt = 2 * bx + 2;
    const __nv_bfloat16 *gkh = Kh + headoff, *gkl = Kl + headoff;
    const __nv_bfloat16 *gvh = Vh + headoff, *gvl = Vl + headoff;

    #pragma unroll
    for (int it = 0; it < 2; it++) {
        int f = tid + it * 256;
        int r = f >> 3, ch = f & 7;
        uint32_t so = kvb + (uint32_t)(r * AT_ROWB + ch * 16);
        size_t go = (size_t)r * Dd + ch * 8;
        cpa16(so,                  gkh + go);
        cpa16(so + AT_TILE_B,      gkl + go);
        cpa16(so + 2 * AT_TILE_B,  gvh + go);
        cpa16(so + 3 * AT_TILE_B,  gvl + go);
    }
    CPA_COMMIT();

    for (int kt = 0; kt < nkt; kt++) {
        __syncthreads();
        if (kt + 1 < nkt) {
            const uint32_t st2 = kvb + (uint32_t)(((kt + 1) & 1) * AT_STAGE_B);
            const size_t kb = (size_t)(kt + 1) * 64 * Dd;
            #pragma unroll
            for (int it = 0; it < 2; it++) {
                int f = tid + it * 256;
                int r = f >> 3, ch = f & 7;
                uint32_t so = st2 + (uint32_t)(r * AT_ROWB + ch * 16);
                size_t go = kb + (size_t)r * Dd + ch * 8;
                cpa16(so,                 gkh + go);
                cpa16(so + AT_TILE_B,     gkl + go);
                cpa16(so + 2 * AT_TILE_B, gvh + go);
                cpa16(so + 3 * AT_TILE_B, gvl + go);
            }
            CPA_COMMIT();
            CPA_WAIT1();
        } else {
            CPA_WAIT0();
        }
        __syncthreads();

        const int k0 = kt * 64;
        const bool active = (k0 <= q0 + 16 * w + 15);
        if (active) {
            const uint32_t stg = kvb + (uint32_t)((kt & 1) * AT_STAGE_B);
            float sacc[8][4];
            #pragma unroll
            for (int i = 0; i < 8; i++)
                #pragma unroll
                for (int e = 0; e < 4; e++) sacc[i][e] = 0.f;

            const uint32_t lb = stg + (uint32_t)((lane & 15) * AT_ROWB
                                                 + (lane >> 4) * 16);
            #pragma unroll
            for (int c = 0; c < 4; c++) {
                uint32_t qh4[4], ql4[4];
                ldm4(qlb + (uint32_t)(c * 32), qh4);
                ldm4(qlb + 18432u + (uint32_t)(c * 32), ql4);
                #pragma unroll
                for (int g = 0; g < 4; g++) {
                    uint32_t kh4[4], kl4[4];
                    uint32_t a = lb + (uint32_t)(g * 16 * AT_ROWB + c * 32);
                    ldm4(a, kh4);
                    ldm4(a + AT_TILE_B, kl4);
                    mma16816(sacc[2*g],   qh4, kh4[0], kh4[2]);
                    mma16816(sacc[2*g+1], qh4, kh4[1], kh4[3]);
                    mma16816(sacc[2*g],   qh4, kl4[0], kl4[2]);
                    mma16816(sacc[2*g+1], qh4, kl4[1], kl4[3]);
                    mma16816(sacc[2*g],   ql4, kh4[0], kh4[2]);
                    mma16816(sacc[2*g+1], ql4, kh4[1], kh4[3]);
                }
            }

            if (k0 + 63 > q0 + 16 * w) {
                #pragma unroll
                for (int nb = 0; nb < 8; nb++) {
                    int col = k0 + nb * 8 + (lane & 3) * 2;
                    if (col     > r0g) sacc[nb][0] = -1e30f;
                    if (col + 1 > r0g) sacc[nb][1] = -1e30f;
                    if (col     > r1g) sacc[nb][2] = -1e30f;
                    if (col + 1 > r1g) sacc[nb][3] = -1e30f;
                }
            }

            float mx0 = -1e30f, mx1 = -1e30f;
            #pragma unroll
            for (int nb = 0; nb < 8; nb++) {
                mx0 = fmaxf(mx0, fmaxf(sacc[nb][0], sacc[nb][1]));
                mx1 = fmaxf(mx1, fmaxf(sacc[nb][2], sacc[nb][3]));
            }
            mx0 = fmaxf(mx0, __shfl_xor_sync(0xffffffffu, mx0, 1));
            mx0 = fmaxf(mx0, __shfl_xor_sync(0xffffffffu, mx0, 2));
            mx1 = fmaxf(mx1, __shfl_xor_sync(0xffffffffu, mx1, 1));
            mx1 = fmaxf(mx1, __shfl_xor_sync(0xffffffffu, mx1, 2));
            const float nm0 = fmaxf(m0, mx0), nm1 = fmaxf(m1, mx1);
            const float a0 = exp2f((m0 - nm0) * CS);
            const float a1 = exp2f((m1 - nm1) * CS);
            m0 = nm0; m1 = nm1;
            const float c0 = nm0 * CS, c1 = nm1 * CS;
            float s0 = 0.f, s1 = 0.f;
            #pragma unroll
            for (int nb = 0; nb < 8; nb++) {
                float p0 = exp2f(fmaf(sacc[nb][0], CS, -c0));
                float p1 = exp2f(fmaf(sacc[nb][1], CS, -c0));
                float p2 = exp2f(fmaf(sacc[nb][2], CS, -c1));
                float p3 = exp2f(fmaf(sacc[nb][3], CS, -c1));
                sacc[nb][0] = p0; sacc[nb][1] = p1;
                sacc[nb][2] = p2; sacc[nb][3] = p3;
                s0 += p0 + p1;
                s1 += p2 + p3;
            }
            s0 += __shfl_xor_sync(0xffffffffu, s0, 1);
            s0 += __shfl_xor_sync(0xffffffffu, s0, 2);
            s1 += __shfl_xor_sync(0xffffffffu, s1, 1);
            s1 += __shfl_xor_sync(0xffffffffu, s1, 2);
            l0 = l0 * a0 + s0;
            l1 = l1 * a1 + s1;
            #pragma unroll
            for (int i = 0; i < 8; i++) {
                oacc[i][0] *= a0; oacc[i][1] *= a0;
                oacc[i][2] *= a1; oacc[i][3] *= a1;
            }

            #pragma unroll
            for (int j = 0; j < 4; j++) {
                uint32_t pa[4], pl[4];
                pack_split(sacc[2*j][0],   sacc[2*j][1],   pa[0], pl[0]);
                pack_split(sacc[2*j][2],   sacc[2*j][3],   pa[1], pl[1]);
                pack_split(sacc[2*j+1][0], sacc[2*j+1][1], pa[2], pl[2]);
                pack_split(sacc[2*j+1][2], sacc[2*j+1][3], pa[3], pl[3]);
                const uint32_t vb = stg + 2 * AT_TILE_B
                    + (uint32_t)((16 * j + (lane & 15)) * AT_ROWB + (lane >> 4) * 16);
                #pragma unroll
                for (int dp = 0; dp < 4; dp++) {
                    uint32_t vh4[4], vl4[4];
                    ldm4t(vb + (uint32_t)(dp * 32), vh4);
                    ldm4t(vb + AT_TILE_B + (uint32_t)(dp * 32), vl4);
                    mma16816(oacc[2*dp],   pa, vh4[0], vh4[1]);
                    mma16816(oacc[2*dp+1], pa, vh4[2], vh4[3]);
                    mma16816(oacc[2*dp],   pa, vl4[0], vl4[1]);
                    mma16816(oacc[2*dp+1], pa, vl4[2], vl4[3]);
                    mma16816(oacc[2*dp],   pl, vh4[0], vh4[1]);
                    mma16816(oacc[2*dp+1], pl, vh4[2], vh4[3]);
                }
            }
        }
    }

    const float i0 = 1.f / l0, i1 = 1.f / l1;
    const size_t ro0 = (size_t)b * Ss * Dd + (size_t)r0g * Dd + (size_t)h * HDd;
    const size_t ro1 = ro0 + 8 * Dd;
    #pragma unroll
    for (int nb = 0; nb < 8; nb++) {
        const int dcol = nb * 8 + (lane & 3) * 2;
        uint32_t hu, lu;
        pack_split(oacc[nb][0] * i0, oacc[nb][1] * i0, hu, lu);
        *(uint32_t*)(Oh + ro0 + dcol) = hu;
        *(uint32_t*)(Ol + ro0 + dcol) = lu;
        pack_split(oacc[nb][2] * i1, oacc[nb][3] * i1, hu, lu);
        *(uint32_t*)(Oh + ro1 + dcol) = hu;
        *(uint32_t*)(Ol + ro1 + dcol) = lu;
    }
}

// ---------------------------------------------------------------------------
// LayerNorm over last dim (1024)
// ---------------------------------------------------------------------------
__global__ __launch_bounds__(256) void ln_kernel(
    const float* __restrict__ X, const float* __restrict__ gamma,
    const float* __restrict__ beta, float* __restrict__ Y)
{
    const int row = blockIdx.x;
    const int t = threadIdx.x;
    const float4 v = ((const float4*)(X + (size_t)row * Dd))[t];

    float s  = v.x + v.y + v.z + v.w;
    float ss = v.x * v.x + v.y * v.y + v.z * v.z + v.w * v.w;
    #pragma unroll
    for (int o = 16; o > 0; o >>= 1) {
        s  += __shfl_xor_sync(0xffffffffu, s,  o);
        ss += __shfl_xor_sync(0xffffffffu, ss, o);
    }
    __shared__ float sh[8][2];
    if ((t & 31) == 0) { sh[t >> 5][0] = s; sh[t >> 5][1] = ss; }
    __syncthreads();
    float ts = 0.f, tss = 0.f;
    #pragma unroll
    for (int i = 0; i < 8; i++) { ts += sh[i][0]; tss += sh[i][1]; }

    const float mu  = ts * (1.0f / Dd);
    const float var = tss * (1.0f / Dd) - mu * mu;
    const float inv = rsqrtf(var + LN_EPS);

    const float4 gg = ((const float4*)gamma)[t];
    const float4 bb = ((const float4*)beta)[t];
    float4 y;
    y.x = (v.x - mu) * inv * gg.x + bb.x;
    y.y = (v.y - mu) * inv * gg.y + bb.y;
    y.z = (v.z - mu) * inv * gg.z + bb.z;
    y.w = (v.w - mu) * inv * gg.w + bb.w;
    ((float4*)(Y + (size_t)row * Dd))[t] = y;
}

// ---------------------------------------------------------------------------
// Launch — 8 kernels total (merged convs; separate reg-safe GEMMs).
// Inputs: q, k, v, wq, wk, wv, wo, gamma, beta, mask (causal; unused).
// ---------------------------------------------------------------------------
extern "C" void kernel_launch(void* const* d_in, const int* in_sizes, int n_in,
                              void* d_out, int out_size)
{
    const float* q     = (const float*)d_in[0];
    const float* k     = (const float*)d_in[1];
    const float* v     = (const float*)d_in[2];
    const float* wq    = (const float*)d_in[3];
    const float* wk    = (const float*)d_in[4];
    const float* wv    = (const float*)d_in[5];
    const float* wo    = (const float*)d_in[6];
    const float* gamma = (const float*)d_in[7];
    const float* beta  = (const float*)d_in[8];
    float* out = (float*)d_out;

    float* gtmp;
    __nv_bfloat16 *gxh, *gxl, *gwth, *gwtl, *gph, *gpl, *goh, *gol;
    cudaGetSymbolAddress((void**)&gtmp, g_tmp);
    cudaGetSymbolAddress((void**)&gxh,  g_xh);
    cudaGetSymbolAddress((void**)&gxl,  g_xl);
    cudaGetSymbolAddress((void**)&gwth, g_wth);
    cudaGetSymbolAddress((void**)&gwtl, g_wtl);
    cudaGetSymbolAddress((void**)&gph,  g_ph);
    cudaGetSymbolAddress((void**)&gpl,  g_pl);
    cudaGetSymbolAddress((void**)&goh,  g_oh);
    cudaGetSymbolAddress((void**)&gol,  g_ol);

    cudaFuncSetAttribute(gemm_tc,
                         cudaFuncAttributeMaxDynamicSharedMemorySize, GEMM_SMEM);
    cudaFuncSetAttribute(attn_tc,
                         cudaFuncAttributeMaxDynamicSharedMemorySize, ATTN2_SMEM);

    const dim3 blk256(256);
    const dim3 ggemm(Dd / 128, MS / 128);     // (8, 32)

    // all conversions up front (2 launches)
    conv_wt_all<<<dim3(Dd / 32, Dd / 32, 4), blk256>>>(wq, wk, wv, wo, gwth, gwtl);
    conv_act_all<<<dim3(MS * Dd / 4 / 256, 1, 3), blk256>>>(q, k, v, gxh, gxl);

    // Q/K/V projections: separate launches, per-launch plane pointers
    gemm_tc<<<ggemm, blk256, GEMM_SMEM>>>(
        gxh,           gxl,           gwth,           gwtl,
        nullptr, nullptr, gph,           gpl);
    gemm_tc<<<ggemm, blk256, GEMM_SMEM>>>(
        gxh + PSZ,     gxl + PSZ,     gwth + WSZ,     gwtl + WSZ,
        nullptr, nullptr, gph + PSZ,     gpl + PSZ);
    gemm_tc<<<ggemm, blk256, GEMM_SMEM>>>(
        gxh + 2 * PSZ, gxl + 2 * PSZ, gwth + 2 * WSZ, gwtl + 2 * WSZ,
        nullptr, nullptr, gph + 2 * PSZ, gpl + 2 * PSZ);

    // flash attention -> split output
    attn_tc<<<dim3(Ss / 128, Hh, Bb), blk256, ATTN2_SMEM>>>(
        gph, gph /*unused dup guard*/ == gph ? gpl : gpl,   // (kept simple below)
        gph + PSZ, gpl + PSZ, gph + 2 * PSZ, gpl + 2 * PSZ, goh, gol);

    // output projection + residual (fp32 out)
    gemm_tc<<<ggemm, blk256, GEMM_SMEM>>>(
        goh, gol, gwth + 3 * WSZ, gwtl + 3 * WSZ, q, gtmp, nullptr, nullptr);

    // LayerNorm
    ln_kernel<<<MS, blk256>>>(gtmp, gamma, beta, out);
}

// round 11
// speedup vs baseline: 1.4296x; 1.3821x over previous
#include <cuda_runtime.h>
#include <cuda_fp16.h>
#include <cstdint>

// Problem constants
#define Bb  2
#define Ss  2048
#define Dd  1024
#define Hh  16
#define HDd 64
#define MS  (Bb*Ss)          // 4096 rows
#define LN_EPS 1e-5f
#define GK 1024
#define PSZ ((size_t)MS * Dd)
#define WSZ ((size_t)Dd * Dd)

// ---------------------------------------------------------------------------
// Scratch (device globals) — fp16 split scheme
// ---------------------------------------------------------------------------
__device__ float g_tmp[MS*Dd];                 // pre-LN
__device__ __half g_xh[3*MS*Dd];               // staged inputs hi (q,k,v planes)
__device__ __half g_xl[3*MS*Dd];               // staged inputs lo
__device__ __half g_wth[4*Dd*Dd];              // W^T hi [N][K] (wq,wk,wv,wo)
__device__ __half g_ph[3*MS*Dd];               // projections hi (Q,K,V planes)
__device__ __half g_pl[3*MS*Dd];               // projections lo (only Q-plane used)
__device__ __half g_oh[MS*Dd], g_ol[MS*Dd];    // attention out split

// ---------------------------------------------------------------------------
// Helpers
// ---------------------------------------------------------------------------
__device__ __forceinline__ uint32_t smem_u32(const void* p) {
    uint32_t a;
    asm("{ .reg .u64 t; cvta.to.shared.u64 t, %1; cvt.u32.u64 %0, t; }"
        : "=r"(a) : "l"(p));
    return a;
}
__device__ __forceinline__ void cpa16(uint32_t s, const void* g) {
    asm volatile("cp.async.cg.shared.global [%0], [%1], 16;" :: "r"(s), "l"(g));
}
#define CPA_COMMIT() asm volatile("cp.async.commit_group;" ::: "memory")
#define CPA_WAIT0()  asm volatile("cp.async.wait_group 0;" ::: "memory")
#define CPA_WAIT1()  asm volatile("cp.async.wait_group 1;" ::: "memory")

__device__ __forceinline__ void ldm4(uint32_t a, uint32_t r[4]) {
    asm volatile("ldmatrix.sync.aligned.m8n8.x4.shared.b16 {%0,%1,%2,%3}, [%4];"
                 : "=r"(r[0]), "=r"(r[1]), "=r"(r[2]), "=r"(r[3]) : "r"(a));
}
__device__ __forceinline__ void ldm4t(uint32_t a, uint32_t r[4]) {
    asm volatile("ldmatrix.sync.aligned.m8n8.x4.trans.shared.b16 {%0,%1,%2,%3}, [%4];"
                 : "=r"(r[0]), "=r"(r[1]), "=r"(r[2]), "=r"(r[3]) : "r"(a));
}
// fp16 HMMA, fp32 accumulate
__device__ __forceinline__ void mma16816(float d[4], const uint32_t a[4],
                                         uint32_t b0, uint32_t b1) {
    asm volatile(
        "mma.sync.aligned.m16n8k16.row.col.f32.f16.f16.f32 "
        "{%0,%1,%2,%3}, {%4,%5,%6,%7}, {%8,%9}, {%0,%1,%2,%3};"
        : "+f"(d[0]), "+f"(d[1]), "+f"(d[2]), "+f"(d[3])
        : "r"(a[0]), "r"(a[1]), "r"(a[2]), "r"(a[3]), "r"(b0), "r"(b1));
}
// split fp32 pair -> fp16x2 (hi) + fp16x2 (lo)
__device__ __forceinline__ void pack_split(float x, float y,
                                           uint32_t& hi, uint32_t& lo) {
    __half hx = __float2half_rn(x), hy = __float2half_rn(y);
    __half lx = __float2half_rn(x - __half2float(hx));
    __half ly = __float2half_rn(y - __half2float(hy));
    hi = (uint32_t)__half_as_ushort(hx) | ((uint32_t)__half_as_ushort(hy) << 16);
    lo = (uint32_t)__half_as_ushort(lx) | ((uint32_t)__half_as_ushort(ly) << 16);
}

// ---------------------------------------------------------------------------
// fp16 2-product HMMA GEMM: C = (Ah + Al) @ Wh  (+resid)
// 256 threads, 128x128 CTA tile, 64x32 warp tile, 2 CTAs/SM.
// SMEM/stage: Ah @0 (10240B), Al @10240, Wh @20480. Stage stride 30720.
// ---------------------------------------------------------------------------
#define GEMM_SMEM 61440

__global__ __launch_bounds__(256, 2)
void gemm_tc(const __half* __restrict__ Ah, const __half* __restrict__ Al,
             const __half* __restrict__ Wh,
             const float* __restrict__ resid, float* __restrict__ C,
             __half* __restrict__ OH, __half* __restrict__ OL)
{
    extern __shared__ __half S[];
    const int tid  = threadIdx.x;
    const int lane = tid & 31;
    const int wid  = tid >> 5;            // 0..7
    const int bm = blockIdx.y * 128;
    const int bn = blockIdx.x * 128;
    const int wm = (wid & 1) * 64;
    const int wn = (wid >> 1) * 32;

    const __half* gA  = Ah + (size_t)bm * GK;
    const __half* gAl = Al + (size_t)bm * GK;
    const __half* gB  = Wh + (size_t)bn * GK;

    const uint32_t sbase = smem_u32(S);

    float d[4][4][4];
    #pragma unroll
    for (int i = 0; i < 4; i++)
        #pragma unroll
        for (int j = 0; j < 4; j++)
            #pragma unroll
            for (int e = 0; e < 4; e++) d[i][j][e] = 0.f;

    const uint32_t acb_row = (uint32_t)(lane & 15);
    const uint32_t acb_col = (uint32_t)((lane >> 4) * 8);

    // prologue: stage 0, k0 = 0
    {
        #pragma unroll
        for (int it = 0; it < 2; it++) {
            int f = tid + it * 256;
            int r = f >> 2;
            int u = f & 3;
            uint32_t so = sbase + (uint32_t)(r * 40 + u * 8) * 2;
            size_t go = (size_t)r * GK + u * 8;
            cpa16(so,          gA  + go);
            cpa16(so + 10240u, gAl + go);
            cpa16(so + 20480u, gB  + go);
        }
        CPA_COMMIT();
        CPA_WAIT0();
        __syncthreads();
    }

    for (int ic = 0; ic < 32; ic++) {
        const int st = ic & 1;
        if (ic + 1 < 32) {
            const int k0 = (ic + 1) * 32;
            const uint32_t sb2 = sbase + (uint32_t)((st ^ 1) * 30720);
            #pragma unroll
            for (int it = 0; it < 2; it++) {
                int f = tid + it * 256;
                int r = f >> 2;
                int u = f & 3;
                uint32_t so = sb2 + (uint32_t)(r * 40 + u * 8) * 2;
                size_t go = (size_t)r * GK + k0 + u * 8;
                cpa16(so,          gA  + go);
                cpa16(so + 10240u, gAl + go);
                cpa16(so + 20480u, gB  + go);
            }
        }
        CPA_COMMIT();

        const uint32_t sb = sbase + (uint32_t)(st * 30720);
        #pragma unroll
        for (int ks = 0; ks < 2; ks++) {
            const uint32_t cb = (uint32_t)(ks * 16) * 2 + acb_col * 2;

            uint32_t ah[4][4], al[4][4], bh[2][4];
            #pragma unroll
            for (int i = 0; i < 4; i++) {
                uint32_t ra = sb + (uint32_t)((wm + i * 16) + acb_row) * 80u + cb;
                ldm4(ra, ah[i]);
                ldm4(ra + 10240u, al[i]);
            }
            #pragma unroll
            for (int nb = 0; nb < 2; nb++)
                ldm4(sb + 20480u + (uint32_t)((wn + nb * 16) + acb_row) * 80u + cb, bh[nb]);

            #pragma unroll
            for (int i = 0; i < 4; i++)
                #pragma unroll
                for (int nb = 0; nb < 2; nb++) {
                    mma16816(d[i][2*nb],     ah[i], bh[nb][0], bh[nb][2]);
                    mma16816(d[i][2*nb + 1], ah[i], bh[nb][1], bh[nb][3]);
                    mma16816(d[i][2*nb],     al[i], bh[nb][0], bh[nb][2]);
                    mma16816(d[i][2*nb + 1], al[i], bh[nb][1], bh[nb][3]);
                }
        }
        CPA_WAIT0();
        __syncthreads();
    }

    const int er = bm + wm + (lane >> 2);
    const int ec = bn + wn + (lane & 3) * 2;
    #pragma unroll
    for (int i = 0; i < 4; i++) {
        const int r1 = er + i * 16;
        #pragma unroll
        for (int jj = 0; jj < 4; jj++) {
            const int c = ec + jj * 8;
            size_t o0 = (size_t)r1 * GK + c;
            size_t o1 = (size_t)(r1 + 8) * GK + c;
            if (OH) {
                uint32_t hu, lu;
                pack_split(d[i][jj][0], d[i][jj][1], hu, lu);
                *(uint32_t*)(OH + o0) = hu;
                *(uint32_t*)(OL + o0) = lu;
                pack_split(d[i][jj][2], d[i][jj][3], hu, lu);
                *(uint32_t*)(OH + o1) = hu;
                *(uint32_t*)(OL + o1) = lu;
            } else {
                float2 v0 = make_float2(d[i][jj][0], d[i][jj][1]);
                float2 v1 = make_float2(d[i][jj][2], d[i][jj][3]);
                if (resid) {
                    float2 q0 = *(const float2*)(resid + o0);
                    float2 q1 = *(const float2*)(resid + o1);
                    v0.x += q0.x; v0.y += q0.y;
                    v1.x += q1.x; v1.y += q1.y;
                }
                *(float2*)(C + o0) = v0;
                *(float2*)(C + o1) = v1;
            }
        }
    }
}

// ---------------------------------------------------------------------------
// fp32 -> fp16 hi/lo split; grid.z selects source (q,k,v) -> plane z
// ---------------------------------------------------------------------------
__global__ __launch_bounds__(256) void conv_act_all(
    const float* __restrict__ X0, const float* __restrict__ X1,
    const float* __restrict__ X2,
    __half* __restrict__ H, __half* __restrict__ L)
{
    const int z = blockIdx.z;
    const float* X = (z == 0) ? X0 : (z == 1) ? X1 : X2;
    size_t i = (size_t)blockIdx.x * 256 + threadIdx.x;
    float4 v = ((const float4*)X)[i];
    float vv[4] = {v.x, v.y, v.z, v.w};
    __half h[4], l[4];
    #pragma unroll
    for (int j = 0; j < 4; j++) {
        h[j] = __float2half_rn(vv[j]);
        l[j] = __float2half_rn(vv[j] - __half2float(h[j]));
    }
    uint64_t hp, lp;
    memcpy(&hp, h, 8); memcpy(&lp, l, 8);
    const size_t zo4 = (size_t)z * (PSZ / 4);
    ((uint64_t*)H)[zo4 + i] = hp;
    ((uint64_t*)L)[zo4 + i] = lp;
}

// ---------------------------------------------------------------------------
// W [K][N] fp32 -> W^T hi fp16 [N][K]; grid.z selects (wq,wk,wv,wo)
// ---------------------------------------------------------------------------
__global__ __launch_bounds__(256) void conv_wt_all(
    const float* __restrict__ W0, const float* __restrict__ W1,
    const float* __restrict__ W2, const float* __restrict__ W3,
    __half* __restrict__ TH)
{
    __shared__ float t[32][33];
    const int z = blockIdx.z;
    const float* W = (z == 0) ? W0 : (z == 1) ? W1 : (z == 2) ? W2 : W3;
    const size_t zw = (size_t)z * WSZ;
    const int bxn = blockIdx.x * 32;
    const int byk = blockIdx.y * 32;
    const int tx = threadIdx.x & 31;
    const int ty4 = (threadIdx.x >> 5) * 4;

    #pragma unroll
    for (int j = 0; j < 4; j++)
        t[ty4 + j][tx] = W[(size_t)(byk + ty4 + j) * Dd + bxn + tx];
    __syncthreads();

    #pragma unroll
    for (int j = 0; j < 4; j++) {
        float x = t[tx][ty4 + j];
        TH[zw + (size_t)(bxn + ty4 + j) * Dd + byk + tx] = __float2half_rn(x);
    }
}

// ---------------------------------------------------------------------------
// fp16 HMMA flash attention (causal), 2-product scheme:
//   S = (Qh+Ql)·Kh,  O = (Ph+Pl)·Vh.
// Q hi/lo persistent in SMEM [0, 36864); K/V hi double-buffer above.
// ---------------------------------------------------------------------------
#define AT_ROWB    144
#define AT_TILE_B  (64 * AT_ROWB)          // 9216
#define AT_KVSTG_B (2 * AT_TILE_B)         // 18432: Kh + Vh
#define AT_Q_B     36864                   // Q hi (18432) + Q lo (18432)
#define ATTN2_SMEM (AT_Q_B + 2 * AT_KVSTG_B)   // 73728
#define CS 0.18033688011112042f            // log2(e)/8

__global__ __launch_bounds__(256, 2) void attn_tc(
    const __half* __restrict__ Qh, const __half* __restrict__ Ql,
    const __half* __restrict__ Kh, const __half* __restrict__ Vh,
    __half* __restrict__ Oh, __half* __restrict__ Ol)
{
    extern __shared__ char smc[];
    const int tid = threadIdx.x;
    const int lane = tid & 31;
    const int w = tid >> 5;
    const int bx = blockIdx.x, h = blockIdx.y, b = blockIdx.z;
    const int q0 = bx * 128;
    const uint32_t sb = smem_u32(smc);
    const uint32_t kvb = sb + AT_Q_B;
    const size_t headoff = (size_t)b * Ss * Dd + (size_t)h * HDd;

    // ---- Q tiles -> persistent SMEM (hi @0, lo @18432)
    {
        const __half* gq  = Qh + headoff + (size_t)q0 * Dd;
        const __half* gql = Ql + headoff + (size_t)q0 * Dd;
        #pragma unroll
        for (int it = 0; it < 4; it++) {
            int f = tid + it * 256;
            int r = f >> 3, ch = f & 7;
            uint32_t so = sb + (uint32_t)(r * AT_ROWB + ch * 16);
            size_t go = (size_t)r * Dd + ch * 8;
            cpa16(so, gq + go);
            cpa16(so + 18432u, gql + go);
        }
        CPA_COMMIT();
        CPA_WAIT0();
    }
    __syncthreads();

    const uint32_t qlb = sb + (uint32_t)((16 * w + (lane & 15)) * AT_ROWB
                                         + (lane >> 4) * 16);

    float oacc[8][4];
    #pragma unroll
    for (int i = 0; i < 8; i++)
        #pragma unroll
        for (int e = 0; e < 4; e++) oacc[i][e] = 0.f;
    float m0 = -1e30f, m1 = -1e30f, l0 = 0.f, l1 = 0.f;
    const int r0g = q0 + 16 * w + (lane >> 2);
    const int r1g = r0g + 8;

    const int nkt = 2 * bx + 2;
    const __half *gkh = Kh + headoff, *gvh = Vh + headoff;

    // prologue: KV tile 0 -> stage 0
    #pragma unroll
    for (int it = 0; it < 2; it++) {
        int f = tid + it * 256;              // 0..511
        int r = f >> 3, ch = f & 7;
        uint32_t so = kvb + (uint32_t)(r * AT_ROWB + ch * 16);
        size_t go = (size_t)r * Dd + ch * 8;
        cpa16(so,             gkh + go);
        cpa16(so + AT_TILE_B, gvh + go);
    }
    CPA_COMMIT();

    for (int kt = 0; kt < nkt; kt++) {
        __syncthreads();
        if (kt + 1 < nkt) {
            const uint32_t st2 = kvb + (uint32_t)(((kt + 1) & 1) * AT_KVSTG_B);
            const size_t kb = (size_t)(kt + 1) * 64 * Dd;
            #pragma unroll
            for (int it = 0; it < 2; it++) {
                int f = tid + it * 256;
                int r = f >> 3, ch = f & 7;
                uint32_t so = st2 + (uint32_t)(r * AT_ROWB + ch * 16);
                size_t go = kb + (size_t)r * Dd + ch * 8;
                cpa16(so,             gkh + go);
                cpa16(so + AT_TILE_B, gvh + go);
            }
            CPA_COMMIT();
            CPA_WAIT1();
        } else {
            CPA_WAIT0();
        }
        __syncthreads();

        const int k0 = kt * 64;
        const bool active = (k0 <= q0 + 16 * w + 15);   // warp-uniform
        if (active) {
            const uint32_t stg = kvb + (uint32_t)((kt & 1) * AT_KVSTG_B);
            float sacc[8][4];
            #pragma unroll
            for (int i = 0; i < 8; i++)
                #pragma unroll
                for (int e = 0; e < 4; e++) sacc[i][e] = 0.f;

            const uint32_t lb = stg + (uint32_t)((lane & 15) * AT_ROWB
                                                 + (lane >> 4) * 16);
            #pragma unroll
            for (int c = 0; c < 4; c++) {
                uint32_t qh4[4], ql4[4];
                ldm4(qlb + (uint32_t)(c * 32), qh4);
                ldm4(qlb + 18432u + (uint32_t)(c * 32), ql4);
                #pragma unroll
                for (int g = 0; g < 4; g++) {
                    uint32_t kh4[4];
                    ldm4(lb + (uint32_t)(g * 16 * AT_ROWB + c * 32), kh4);
                    mma16816(sacc[2*g],   qh4, kh4[0], kh4[2]);
                    mma16816(sacc[2*g+1], qh4, kh4[1], kh4[3]);
                    mma16816(sacc[2*g],   ql4, kh4[0], kh4[2]);
                    mma16816(sacc[2*g+1], ql4, kh4[1], kh4[3]);
                }
            }

            if (k0 + 63 > q0 + 16 * w) {
                #pragma unroll
                for (int nb = 0; nb < 8; nb++) {
                    int col = k0 + nb * 8 + (lane & 3) * 2;
                    if (col     > r0g) sacc[nb][0] = -1e30f;
                    if (col + 1 > r0g) sacc[nb][1] = -1e30f;
                    if (col     > r1g) sacc[nb][2] = -1e30f;
                    if (col + 1 > r1g) sacc[nb][3] = -1e30f;
                }
            }

            float mx0 = -1e30f, mx1 = -1e30f;
            #pragma unroll
            for (int nb = 0; nb < 8; nb++) {
                mx0 = fmaxf(mx0, fmaxf(sacc[nb][0], sacc[nb][1]));
                mx1 = fmaxf(mx1, fmaxf(sacc[nb][2], sacc[nb][3]));
            }
            mx0 = fmaxf(mx0, __shfl_xor_sync(0xffffffffu, mx0, 1));
            mx0 = fmaxf(mx0, __shfl_xor_sync(0xffffffffu, mx0, 2));
            mx1 = fmaxf(mx1, __shfl_xor_sync(0xffffffffu, mx1, 1));
            mx1 = fmaxf(mx1, __shfl_xor_sync(0xffffffffu, mx1, 2));
            const float nm0 = fmaxf(m0, mx0), nm1 = fmaxf(m1, mx1);
            const float a0 = exp2f((m0 - nm0) * CS);
            const float a1 = exp2f((m1 - nm1) * CS);
            m0 = nm0; m1 = nm1;
            const float c0 = nm0 * CS, c1 = nm1 * CS;
            float s0 = 0.f, s1 = 0.f;
            #pragma unroll
            for (int nb = 0; nb < 8; nb++) {
                float p0 = exp2f(fmaf(sacc[nb][0], CS, -c0));
                float p1 = exp2f(fmaf(sacc[nb][1], CS, -c0));
                float p2 = exp2f(fmaf(sacc[nb][2], CS, -c1));
                float p3 = exp2f(fmaf(sacc[nb][3], CS, -c1));
                sacc[nb][0] = p0; sacc[nb][1] = p1;
                sacc[nb][2] = p2; sacc[nb][3] = p3;
                s0 += p0 + p1;
                s1 += p2 + p3;
            }
            s0 += __shfl_xor_sync(0xffffffffu, s0, 1);
            s0 += __shfl_xor_sync(0xffffffffu, s0, 2);
            s1 += __shfl_xor_sync(0xffffffffu, s1, 1);
            s1 += __shfl_xor_sync(0xffffffffu, s1, 2);
            l0 = l0 * a0 + s0;
            l1 = l1 * a1 + s1;
            #pragma unroll
            for (int i = 0; i < 8; i++) {
                oacc[i][0] *= a0; oacc[i][1] *= a0;
                oacc[i][2] *= a1; oacc[i][3] *= a1;
            }

            // O += (Ph + Pl) · Vh
            #pragma unroll
            for (int j = 0; j < 4; j++) {
                uint32_t pa[4], pl[4];
                pack_split(sacc[2*j][0],   sacc[2*j][1],   pa[0], pl[0]);
                pack_split(sacc[2*j][2],   sacc[2*j][3],   pa[1], pl[1]);
                pack_split(sacc[2*j+1][0], sacc[2*j+1][1], pa[2], pl[2]);
                pack_split(sacc[2*j+1][2], sacc[2*j+1][3], pa[3], pl[3]);
                const uint32_t vb = stg + AT_TILE_B
                    + (uint32_t)((16 * j + (lane & 15)) * AT_ROWB + (lane >> 4) * 16);
                #pragma unroll
                for (int dp = 0; dp < 4; dp++) {
                    uint32_t vh4[4];
                    ldm4t(vb + (uint32_t)(dp * 32), vh4);
                    mma16816(oacc[2*dp],   pa, vh4[0], vh4[1]);
                    mma16816(oacc[2*dp+1], pa, vh4[2], vh4[3]);
                    mma16816(oacc[2*dp],   pl, vh4[0], vh4[1]);
                    mma16816(oacc[2*dp+1], pl, vh4[2], vh4[3]);
                }
            }
        }
    }

    const float i0 = 1.f / l0, i1 = 1.f / l1;
    const size_t ro0 = (size_t)b * Ss * Dd + (size_t)r0g * Dd + (size_t)h * HDd;
    const size_t ro1 = ro0 + 8 * Dd;
    #pragma unroll
    for (int nb = 0; nb < 8; nb++) {
        const int dcol = nb * 8 + (lane & 3) * 2;
        uint32_t hu, lu;
        pack_split(oacc[nb][0] * i0, oacc[nb][1] * i0, hu, lu);
        *(uint32_t*)(Oh + ro0 + dcol) = hu;
        *(uint32_t*)(Ol + ro0 + dcol) = lu;
        pack_split(oacc[nb][2] * i1, oacc[nb][3] * i1, hu, lu);
        *(uint32_t*)(Oh + ro1 + dcol) = hu;
        *(uint32_t*)(Ol + ro1 + dcol) = lu;
    }
}

// ---------------------------------------------------------------------------
// LayerNorm over last dim (1024)
// ---------------------------------------------------------------------------
__global__ __launch_bounds__(256) void ln_kernel(
    const float* __restrict__ X, const float* __restrict__ gamma,
    const float* __restrict__ beta, float* __restrict__ Y)
{
    const int row = blockIdx.x;
    const int t = threadIdx.x;
    const float4 v = ((const float4*)(X + (size_t)row * Dd))[t];

    float s  = v.x + v.y + v.z + v.w;
    float ss = v.x * v.x + v.y * v.y + v.z * v.z + v.w * v.w;
    #pragma unroll
    for (int o = 16; o > 0; o >>= 1) {
        s  += __shfl_xor_sync(0xffffffffu, s,  o);
        ss += __shfl_xor_sync(0xffffffffu, ss, o);
    }
    __shared__ float sh[8][2];
    if ((t & 31) == 0) { sh[t >> 5][0] = s; sh[t >> 5][1] = ss; }
    __syncthreads();
    float ts = 0.f, tss = 0.f;
    #pragma unroll
    for (int i = 0; i < 8; i++) { ts += sh[i][0]; tss += sh[i][1]; }

    const float mu  = ts * (1.0f / Dd);
    const float var = tss * (1.0f / Dd) - mu * mu;
    const float inv = rsqrtf(var + LN_EPS);

    const float4 gg = ((const float4*)gamma)[t];
    const float4 bb = ((const float4*)beta)[t];
    float4 y;
    y.x = (v.x - mu) * inv * gg.x + bb.x;
    y.y = (v.y - mu) * inv * gg.y + bb.y;
    y.z = (v.z - mu) * inv * gg.z + bb.z;
    y.w = (v.w - mu) * inv * gg.w + bb.w;
    ((float4*)(Y + (size_t)row * Dd))[t] = y;
}

// ---------------------------------------------------------------------------
// Launch. Inputs: q, k, v, wq, wk, wv, wo, gamma, beta, mask (causal; unused).
// ---------------------------------------------------------------------------
extern "C" void kernel_launch(void* const* d_in, const int* in_sizes, int n_in,
                              void* d_out, int out_size)
{
    const float* q     = (const float*)d_in[0];
    const float* k     = (const float*)d_in[1];
    const float* v     = (const float*)d_in[2];
    const float* wq    = (const float*)d_in[3];
    const float* wk    = (const float*)d_in[4];
    const float* wv    = (const float*)d_in[5];
    const float* wo    = (const float*)d_in[6];
    const float* gamma = (const float*)d_in[7];
    const float* beta  = (const float*)d_in[8];
    float* out = (float*)d_out;

    float* gtmp;
    __half *gxh, *gxl, *gwth, *gph, *gpl, *goh, *gol;
    cudaGetSymbolAddress((void**)&gtmp, g_tmp);
    cudaGetSymbolAddress((void**)&gxh,  g_xh);
    cudaGetSymbolAddress((void**)&gxl,  g_xl);
    cudaGetSymbolAddress((void**)&gwth, g_wth);
    cudaGetSymbolAddress((void**)&gph,  g_ph);
    cudaGetSymbolAddress((void**)&gpl,  g_pl);
    cudaGetSymbolAddress((void**)&goh,  g_oh);
    cudaGetSymbolAddress((void**)&gol,  g_ol);

    cudaFuncSetAttribute(gemm_tc,
                         cudaFuncAttributeMaxDynamicSharedMemorySize, GEMM_SMEM);
    cudaFuncSetAttribute(attn_tc,
                         cudaFuncAttributeMaxDynamicSharedMemorySize, ATTN2_SMEM);

    const dim3 blk256(256);
    const dim3 ggemm(Dd / 128, MS / 128);     // (8, 32)

    // conversions up front (2 launches)
    conv_wt_all<<<dim3(Dd / 32, Dd / 32, 4), blk256>>>(wq, wk, wv, wo, gwth);
    conv_act_all<<<dim3(MS * Dd / 4 / 256, 1, 3), blk256>>>(q, k, v, gxh, gxl);

    // Q/K/V projections (split fp16 outputs)
    gemm_tc<<<ggemm, blk256, GEMM_SMEM>>>(
        gxh,           gxl,           gwth,
        nullptr, nullptr, gph,           gpl);
    gemm_tc<<<ggemm, blk256, GEMM_SMEM>>>(
        gxh + PSZ,     gxl + PSZ,     gwth + WSZ,
        nullptr, nullptr, gph + PSZ,     gpl + PSZ);
    gemm_tc<<<ggemm, blk256, GEMM_SMEM>>>(
        gxh + 2 * PSZ, gxl + 2 * PSZ, gwth + 2 * WSZ,
        nullptr, nullptr, gph + 2 * PSZ, gpl + 2 * PSZ);

    // flash attention: Q hi+lo, K hi, V hi -> O hi+lo
    attn_tc<<<dim3(Ss / 128, Hh, Bb), blk256, ATTN2_SMEM>>>(
        gph, gpl, gph + PSZ, gph + 2 * PSZ, goh, gol);

    // output projection + residual (fp32 out)
    gemm_tc<<<ggemm, blk256, GEMM_SMEM>>>(
        goh, gol, gwth + 3 * WSZ, q, gtmp, nullptr, nullptr);

    // LayerNorm
    ln_kernel<<<MS, blk256>>>(gtmp, gamma, beta, out);
}

// round 12
// speedup vs baseline: 1.9547x; 1.3673x over previous
#include <cuda_runtime.h>
#include <cuda_fp16.h>
#include <cstdint>

// Problem constants
#define Bb  2
#define Ss  2048
#define Dd  1024
#define Hh  16
#define HDd 64
#define MS  (Bb*Ss)          // 4096 rows
#define LN_EPS 1e-5f
#define GK 1024
#define PSZ ((size_t)MS * Dd)
#define WSZ ((size_t)Dd * Dd)

// ---------------------------------------------------------------------------
// Scratch (device globals)
// ---------------------------------------------------------------------------
__device__ float g_tmp[MS*Dd];                 // pre-LN
__device__ __half g_xh[3*MS*Dd];               // staged inputs (q,k,v planes, fp16)
__device__ __half g_wth[4*Dd*Dd];              // W^T [N][K] fp16 (wq,wk,wv,wo)
__device__ __half g_ph[3*MS*Dd];               // projections hi (Q,K,V planes)
__device__ __half g_pl[3*MS*Dd];               // projections lo (Q-plane used)
__device__ __half g_oh[MS*Dd];                 // attention out (fp16)

// ---------------------------------------------------------------------------
// Helpers
// ---------------------------------------------------------------------------
__device__ __forceinline__ uint32_t smem_u32(const void* p) {
    uint32_t a;
    asm("{ .reg .u64 t; cvta.to.shared.u64 t, %1; cvt.u32.u64 %0, t; }"
        : "=r"(a) : "l"(p));
    return a;
}
__device__ __forceinline__ void cpa16(uint32_t s, const void* g) {
    asm volatile("cp.async.cg.shared.global [%0], [%1], 16;" :: "r"(s), "l"(g));
}
#define CPA_COMMIT() asm volatile("cp.async.commit_group;" ::: "memory")
#define CPA_WAIT0()  asm volatile("cp.async.wait_group 0;" ::: "memory")
#define CPA_WAIT1()  asm volatile("cp.async.wait_group 1;" ::: "memory")

__device__ __forceinline__ void ldm4(uint32_t a, uint32_t r[4]) {
    asm volatile("ldmatrix.sync.aligned.m8n8.x4.shared.b16 {%0,%1,%2,%3}, [%4];"
                 : "=r"(r[0]), "=r"(r[1]), "=r"(r[2]), "=r"(r[3]) : "r"(a));
}
__device__ __forceinline__ void ldm4t(uint32_t a, uint32_t r[4]) {
    asm volatile("ldmatrix.sync.aligned.m8n8.x4.trans.shared.b16 {%0,%1,%2,%3}, [%4];"
                 : "=r"(r[0]), "=r"(r[1]), "=r"(r[2]), "=r"(r[3]) : "r"(a));
}
// fp16 HMMA, fp32 accumulate
__device__ __forceinline__ void mma16816(float d[4], const uint32_t a[4],
                                         uint32_t b0, uint32_t b1) {
    asm volatile(
        "mma.sync.aligned.m16n8k16.row.col.f32.f16.f16.f32 "
        "{%0,%1,%2,%3}, {%4,%5,%6,%7}, {%8,%9}, {%0,%1,%2,%3};"
        : "+f"(d[0]), "+f"(d[1]), "+f"(d[2]), "+f"(d[3])
        : "r"(a[0]), "r"(a[1]), "r"(a[2]), "r"(a[3]), "r"(b0), "r"(b1));
}
__device__ __forceinline__ void pack_split(float x, float y,
                                           uint32_t& hi, uint32_t& lo) {
    __half hx = __float2half_rn(x), hy = __float2half_rn(y);
    __half lx = __float2half_rn(x - __half2float(hx));
    __half ly = __float2half_rn(y - __half2float(hy));
    hi = (uint32_t)__half_as_ushort(hx) | ((uint32_t)__half_as_ushort(hy) << 16);
    lo = (uint32_t)__half_as_ushort(lx) | ((uint32_t)__half_as_ushort(ly) << 16);
}
__device__ __forceinline__ uint32_t pack_h2(float x, float y) {
    __half hx = __float2half_rn(x), hy = __float2half_rn(y);
    return (uint32_t)__half_as_ushort(hx) | ((uint32_t)__half_as_ushort(hy) << 16);
}

// ---------------------------------------------------------------------------
// fp16 single-product HMMA GEMM: C = A @ Wh (+resid)
// 256 threads, 128x128 CTA tile, 64x32 warp tile, 2 CTAs/SM.
// SMEM/stage: A @0 (10240B), Wh @10240. Stage stride 20480; 2 stages.
// ---------------------------------------------------------------------------
#define GEMM_SMEM 40960

__global__ __launch_bounds__(256, 2)
void gemm_tc(const __half* __restrict__ Ah,
             const __half* __restrict__ Wh,
             const float* __restrict__ resid, float* __restrict__ C,
             __half* __restrict__ OH, __half* __restrict__ OL)
{
    extern __shared__ __half S[];
    const int tid  = threadIdx.x;
    const int lane = tid & 31;
    const int wid  = tid >> 5;            // 0..7
    const int bm = blockIdx.y * 128;
    const int bn = blockIdx.x * 128;
    const int wm = (wid & 1) * 64;
    const int wn = (wid >> 1) * 32;

    const __half* gA = Ah + (size_t)bm * GK;
    const __half* gB = Wh + (size_t)bn * GK;

    const uint32_t sbase = smem_u32(S);

    float d[4][4][4];
    #pragma unroll
    for (int i = 0; i < 4; i++)
        #pragma unroll
        for (int j = 0; j < 4; j++)
            #pragma unroll
            for (int e = 0; e < 4; e++) d[i][j][e] = 0.f;

    const uint32_t acb_row = (uint32_t)(lane & 15);
    const uint32_t acb_col = (uint32_t)((lane >> 4) * 8);

    // prologue: stage 0, k0 = 0
    {
        #pragma unroll
        for (int it = 0; it < 2; it++) {
            int f = tid + it * 256;
            int r = f >> 2;
            int u = f & 3;
            uint32_t so = sbase + (uint32_t)(r * 40 + u * 8) * 2;
            size_t go = (size_t)r * GK + u * 8;
            cpa16(so,          gA + go);
            cpa16(so + 10240u, gB + go);
        }
        CPA_COMMIT();
        CPA_WAIT0();
        __syncthreads();
    }

    for (int ic = 0; ic < 32; ic++) {
        const int st = ic & 1;
        if (ic + 1 < 32) {
            const int k0 = (ic + 1) * 32;
            const uint32_t sb2 = sbase + (uint32_t)((st ^ 1) * 20480);
            #pragma unroll
            for (int it = 0; it < 2; it++) {
                int f = tid + it * 256;
                int r = f >> 2;
                int u = f & 3;
                uint32_t so = sb2 + (uint32_t)(r * 40 + u * 8) * 2;
                size_t go = (size_t)r * GK + k0 + u * 8;
                cpa16(so,          gA + go);
                cpa16(so + 10240u, gB + go);
            }
        }
        CPA_COMMIT();

        const uint32_t sb = sbase + (uint32_t)(st * 20480);
        #pragma unroll
        for (int ks = 0; ks < 2; ks++) {
            const uint32_t cb = (uint32_t)(ks * 16) * 2 + acb_col * 2;

            uint32_t ah[4][4], bh[2][4];
            #pragma unroll
            for (int i = 0; i < 4; i++)
                ldm4(sb + (uint32_t)((wm + i * 16) + acb_row) * 80u + cb, ah[i]);
            #pragma unroll
            for (int nb = 0; nb < 2; nb++)
                ldm4(sb + 10240u + (uint32_t)((wn + nb * 16) + acb_row) * 80u + cb, bh[nb]);

            #pragma unroll
            for (int i = 0; i < 4; i++)
                #pragma unroll
                for (int nb = 0; nb < 2; nb++) {
                    mma16816(d[i][2*nb],     ah[i], bh[nb][0], bh[nb][2]);
                    mma16816(d[i][2*nb + 1], ah[i], bh[nb][1], bh[nb][3]);
                }
        }
        CPA_WAIT0();
        __syncthreads();
    }

    const int er = bm + wm + (lane >> 2);
    const int ec = bn + wn + (lane & 3) * 2;
    #pragma unroll
    for (int i = 0; i < 4; i++) {
        const int r1 = er + i * 16;
        #pragma unroll
        for (int jj = 0; jj < 4; jj++) {
            const int c = ec + jj * 8;
            size_t o0 = (size_t)r1 * GK + c;
            size_t o1 = (size_t)(r1 + 8) * GK + c;
            if (OH) {
                uint32_t hu, lu;
                pack_split(d[i][jj][0], d[i][jj][1], hu, lu);
                *(uint32_t*)(OH + o0) = hu;
                *(uint32_t*)(OL + o0) = lu;
                pack_split(d[i][jj][2], d[i][jj][3], hu, lu);
                *(uint32_t*)(OH + o1) = hu;
                *(uint32_t*)(OL + o1) = lu;
            } else {
                float2 v0 = make_float2(d[i][jj][0], d[i][jj][1]);
                float2 v1 = make_float2(d[i][jj][2], d[i][jj][3]);
                if (resid) {
                    float2 q0 = *(const float2*)(resid + o0);
                    float2 q1 = *(const float2*)(resid + o1);
                    v0.x += q0.x; v0.y += q0.y;
                    v1.x += q1.x; v1.y += q1.y;
                }
                *(float2*)(C + o0) = v0;
                *(float2*)(C + o1) = v1;
            }
        }
    }
}

// ---------------------------------------------------------------------------
// fp32 -> fp16 (single); grid.z selects source (q,k,v) -> plane z
// ---------------------------------------------------------------------------
__global__ __launch_bounds__(256) void conv_act_all(
    const float* __restrict__ X0, const float* __restrict__ X1,
    const float* __restrict__ X2, __half* __restrict__ H)
{
    const int z = blockIdx.z;
    const float* X = (z == 0) ? X0 : (z == 1) ? X1 : X2;
    size_t i = (size_t)blockIdx.x * 256 + threadIdx.x;
    float4 v = ((const float4*)X)[i];
    __half h[4];
    h[0] = __float2half_rn(v.x);
    h[1] = __float2half_rn(v.y);
    h[2] = __float2half_rn(v.z);
    h[3] = __float2half_rn(v.w);
    uint64_t hp;
    memcpy(&hp, h, 8);
    ((uint64_t*)H)[(size_t)z * (PSZ / 4) + i] = hp;
}

// ---------------------------------------------------------------------------
// W [K][N] fp32 -> W^T fp16 [N][K]; grid.z selects (wq,wk,wv,wo)
// ---------------------------------------------------------------------------
__global__ __launch_bounds__(256) void conv_wt_all(
    const float* __restrict__ W0, const float* __restrict__ W1,
    const float* __restrict__ W2, const float* __restrict__ W3,
    __half* __restrict__ TH)
{
    __shared__ float t[32][33];
    const int z = blockIdx.z;
    const float* W = (z == 0) ? W0 : (z == 1) ? W1 : (z == 2) ? W2 : W3;
    const size_t zw = (size_t)z * WSZ;
    const int bxn = blockIdx.x * 32;
    const int byk = blockIdx.y * 32;
    const int tx = threadIdx.x & 31;
    const int ty4 = (threadIdx.x >> 5) * 4;

    #pragma unroll
    for (int j = 0; j < 4; j++)
        t[ty4 + j][tx] = W[(size_t)(byk + ty4 + j) * Dd + bxn + tx];
    __syncthreads();

    #pragma unroll
    for (int j = 0; j < 4; j++)
        TH[zw + (size_t)(bxn + ty4 + j) * Dd + byk + tx] =
            __float2half_rn(t[tx][ty4 + j]);
}

// ---------------------------------------------------------------------------
// fp16 HMMA flash attention (causal), 2-product S and O:
//   S = (Qh+Ql)·Kh,  O = (Ph+Pl)·Vh.  Output single fp16 O.
// Q hi/lo persistent in SMEM [0, 36864); K/V double-buffer above.
// ---------------------------------------------------------------------------
#define AT_ROWB    144
#define AT_TILE_B  (64 * AT_ROWB)          // 9216
#define AT_KVSTG_B (2 * AT_TILE_B)         // 18432: Kh + Vh
#define AT_Q_B     36864
#define ATTN2_SMEM (AT_Q_B + 2 * AT_KVSTG_B)   // 73728
#define CS 0.18033688011112042f            // log2(e)/8

__global__ __launch_bounds__(256, 2) void attn_tc(
    const __half* __restrict__ Qh, const __half* __restrict__ Ql,
    const __half* __restrict__ Kh, const __half* __restrict__ Vh,
    __half* __restrict__ Oh)
{
    extern __shared__ char smc[];
    const int tid = threadIdx.x;
    const int lane = tid & 31;
    const int w = tid >> 5;
    const int bx = blockIdx.x, h = blockIdx.y, b = blockIdx.z;
    const int q0 = bx * 128;
    const uint32_t sb = smem_u32(smc);
    const uint32_t kvb = sb + AT_Q_B;
    const size_t headoff = (size_t)b * Ss * Dd + (size_t)h * HDd;

    {
        const __half* gq  = Qh + headoff + (size_t)q0 * Dd;
        const __half* gql = Ql + headoff + (size_t)q0 * Dd;
        #pragma unroll
        for (int it = 0; it < 4; it++) {
            int f = tid + it * 256;
            int r = f >> 3, ch = f & 7;
            uint32_t so = sb + (uint32_t)(r * AT_ROWB + ch * 16);
            size_t go = (size_t)r * Dd + ch * 8;
            cpa16(so, gq + go);
            cpa16(so + 18432u, gql + go);
        }
        CPA_COMMIT();
        CPA_WAIT0();
    }
    __syncthreads();

    const uint32_t qlb = sb + (uint32_t)((16 * w + (lane & 15)) * AT_ROWB
                                         + (lane >> 4) * 16);

    float oacc[8][4];
    #pragma unroll
    for (int i = 0; i < 8; i++)
        #pragma unroll
        for (int e = 0; e < 4; e++) oacc[i][e] = 0.f;
    float m0 = -1e30f, m1 = -1e30f, l0 = 0.f, l1 = 0.f;
    const int r0g = q0 + 16 * w + (lane >> 2);
    const int r1g = r0g + 8;

    const int nkt = 2 * bx + 2;
    const __half *gkh = Kh + headoff, *gvh = Vh + headoff;

    #pragma unroll
    for (int it = 0; it < 2; it++) {
        int f = tid + it * 256;
        int r = f >> 3, ch = f & 7;
        uint32_t so = kvb + (uint32_t)(r * AT_ROWB + ch * 16);
        size_t go = (size_t)r * Dd + ch * 8;
        cpa16(so,             gkh + go);
        cpa16(so + AT_TILE_B, gvh + go);
    }
    CPA_COMMIT();

    for (int kt = 0; kt < nkt; kt++) {
        __syncthreads();
        if (kt + 1 < nkt) {
            const uint32_t st2 = kvb + (uint32_t)(((kt + 1) & 1) * AT_KVSTG_B);
            const size_t kb = (size_t)(kt + 1) * 64 * Dd;
            #pragma unroll
            for (int it = 0; it < 2; it++) {
                int f = tid + it * 256;
                int r = f >> 3, ch = f & 7;
                uint32_t so = st2 + (uint32_t)(r * AT_ROWB + ch * 16);
                size_t go = kb + (size_t)r * Dd + ch * 8;
                cpa16(so,             gkh + go);
                cpa16(so + AT_TILE_B, gvh + go);
            }
            CPA_COMMIT();
            CPA_WAIT1();
        } else {
            CPA_WAIT0();
        }
        __syncthreads();

        const int k0 = kt * 64;
        const bool active = (k0 <= q0 + 16 * w + 15);   // warp-uniform
        if (active) {
            const uint32_t stg = kvb + (uint32_t)((kt & 1) * AT_KVSTG_B);
            float sacc[8][4];
            #pragma unroll
            for (int i = 0; i < 8; i++)
                #pragma unroll
                for (int e = 0; e < 4; e++) sacc[i][e] = 0.f;

            const uint32_t lb = stg + (uint32_t)((lane & 15) * AT_ROWB
                                                 + (lane >> 4) * 16);
            #pragma unroll
            for (int c = 0; c < 4; c++) {
                uint32_t qh4[4], ql4[4];
                ldm4(qlb + (uint32_t)(c * 32), qh4);
                ldm4(qlb + 18432u + (uint32_t)(c * 32), ql4);
                #pragma unroll
                for (int g = 0; g < 4; g++) {
                    uint32_t kh4[4];
                    ldm4(lb + (uint32_t)(g * 16 * AT_ROWB + c * 32), kh4);
                    mma16816(sacc[2*g],   qh4, kh4[0], kh4[2]);
                    mma16816(sacc[2*g+1], qh4, kh4[1], kh4[3]);
                    mma16816(sacc[2*g],   ql4, kh4[0], kh4[2]);
                    mma16816(sacc[2*g+1], ql4, kh4[1], kh4[3]);
                }
            }

            if (k0 + 63 > q0 + 16 * w) {
                #pragma unroll
                for (int nb = 0; nb < 8; nb++) {
                    int col = k0 + nb * 8 + (lane & 3) * 2;
                    if (col     > r0g) sacc[nb][0] = -1e30f;
                    if (col + 1 > r0g) sacc[nb][1] = -1e30f;
                    if (col     > r1g) sacc[nb][2] = -1e30f;
                    if (col + 1 > r1g) sacc[nb][3] = -1e30f;
                }
            }

            float mx0 = -1e30f, mx1 = -1e30f;
            #pragma unroll
            for (int nb = 0; nb < 8; nb++) {
                mx0 = fmaxf(mx0, fmaxf(sacc[nb][0], sacc[nb][1]));
                mx1 = fmaxf(mx1, fmaxf(sacc[nb][2], sacc[nb][3]));
            }
            mx0 = fmaxf(mx0, __shfl_xor_sync(0xffffffffu, mx0, 1));
            mx0 = fmaxf(mx0, __shfl_xor_sync(0xffffffffu, mx0, 2));
            mx1 = fmaxf(mx1, __shfl_xor_sync(0xffffffffu, mx1, 1));
            mx1 = fmaxf(mx1, __shfl_xor_sync(0xffffffffu, mx1, 2));
            const float nm0 = fmaxf(m0, mx0), nm1 = fmaxf(m1, mx1);
            const float a0 = exp2f((m0 - nm0) * CS);
            const float a1 = exp2f((m1 - nm1) * CS);
            m0 = nm0; m1 = nm1;
            const float c0 = nm0 * CS, c1 = nm1 * CS;
            float s0 = 0.f, s1 = 0.f;
            #pragma unroll
            for (int nb = 0; nb < 8; nb++) {
                float p0 = exp2f(fmaf(sacc[nb][0], CS, -c0));
                float p1 = exp2f(fmaf(sacc[nb][1], CS, -c0));
                float p2 = exp2f(fmaf(sacc[nb][2], CS, -c1));
                float p3 = exp2f(fmaf(sacc[nb][3], CS, -c1));
                sacc[nb][0] = p0; sacc[nb][1] = p1;
                sacc[nb][2] = p2; sacc[nb][3] = p3;
                s0 += p0 + p1;
                s1 += p2 + p3;
            }
            s0 += __shfl_xor_sync(0xffffffffu, s0, 1);
            s0 += __shfl_xor_sync(0xffffffffu, s0, 2);
            s1 += __shfl_xor_sync(0xffffffffu, s1, 1);
            s1 += __shfl_xor_sync(0xffffffffu, s1, 2);
            l0 = l0 * a0 + s0;
            l1 = l1 * a1 + s1;
            #pragma unroll
            for (int i = 0; i < 8; i++) {
                oacc[i][0] *= a0; oacc[i][1] *= a0;
                oacc[i][2] *= a1; oacc[i][3] *= a1;
            }

            // O += (Ph + Pl) · Vh
            #pragma unroll
            for (int j = 0; j < 4; j++) {
                uint32_t pa[4], pl[4];
                pack_split(sacc[2*j][0],   sacc[2*j][1],   pa[0], pl[0]);
                pack_split(sacc[2*j][2],   sacc[2*j][3],   pa[1], pl[1]);
                pack_split(sacc[2*j+1][0], sacc[2*j+1][1], pa[2], pl[2]);
                pack_split(sacc[2*j+1][2], sacc[2*j+1][3], pa[3], pl[3]);
                const uint32_t vb = stg + AT_TILE_B
                    + (uint32_t)((16 * j + (lane & 15)) * AT_ROWB + (lane >> 4) * 16);
                #pragma unroll
                for (int dp = 0; dp < 4; dp++) {
                    uint32_t vh4[4];
                    ldm4t(vb + (uint32_t)(dp * 32), vh4);
                    mma16816(oacc[2*dp],   pa, vh4[0], vh4[1]);
                    mma16816(oacc[2*dp+1], pa, vh4[2], vh4[3]);
                    mma16816(oacc[2*dp],   pl, vh4[0], vh4[1]);
                    mma16816(oacc[2*dp+1], pl, vh4[2], vh4[3]);
                }
            }
        }
    }

    const float i0 = 1.f / l0, i1 = 1.f / l1;
    const size_t ro0 = (size_t)b * Ss * Dd + (size_t)r0g * Dd + (size_t)h * HDd;
    const size_t ro1 = ro0 + 8 * Dd;
    #pragma unroll
    for (int nb = 0; nb < 8; nb++) {
        const int dcol = nb * 8 + (lane & 3) * 2;
        *(uint32_t*)(Oh + ro0 + dcol) = pack_h2(oacc[nb][0] * i0, oacc[nb][1] * i0);
        *(uint32_t*)(Oh + ro1 + dcol) = pack_h2(oacc[nb][2] * i1, oacc[nb][3] * i1);
    }
}

// ---------------------------------------------------------------------------
// LayerNorm over last dim (1024)
// ---------------------------------------------------------------------------
__global__ __launch_bounds__(256) void ln_kernel(
    const float* __restrict__ X, const float* __restrict__ gamma,
    const float* __restrict__ beta, float* __restrict__ Y)
{
    const int row = blockIdx.x;
    const int t = threadIdx.x;
    const float4 v = ((const float4*)(X + (size_t)row * Dd))[t];

    float s  = v.x + v.y + v.z + v.w;
    float ss = v.x * v.x + v.y * v.y + v.z * v.z + v.w * v.w;
    #pragma unroll
    for (int o = 16; o > 0; o >>= 1) {
        s  += __shfl_xor_sync(0xffffffffu, s,  o);
        ss += __shfl_xor_sync(0xffffffffu, ss, o);
    }
    __shared__ float sh[8][2];
    if ((t & 31) == 0) { sh[t >> 5][0] = s; sh[t >> 5][1] = ss; }
    __syncthreads();
    float ts = 0.f, tss = 0.f;
    #pragma unroll
    for (int i = 0; i < 8; i++) { ts += sh[i][0]; tss += sh[i][1]; }

    const float mu  = ts * (1.0f / Dd);
    const float var = tss * (1.0f / Dd) - mu * mu;
    const float inv = rsqrtf(var + LN_EPS);

    const float4 gg = ((const float4*)gamma)[t];
    const float4 bb = ((const float4*)beta)[t];
    float4 y;
    y.x = (v.x - mu) * inv * gg.x + bb.x;
    y.y = (v.y - mu) * inv * gg.y + bb.y;
    y.z = (v.z - mu) * inv * gg.z + bb.z;
    y.w = (v.w - mu) * inv * gg.w + bb.w;
    ((float4*)(Y + (size_t)row * Dd))[t] = y;
}

// ---------------------------------------------------------------------------
// Launch. Inputs: q, k, v, wq, wk, wv, wo, gamma, beta, mask (causal; unused).
// ---------------------------------------------------------------------------
extern "C" void kernel_launch(void* const* d_in, const int* in_sizes, int n_in,
                              void* d_out, int out_size)
{
    const float* q     = (const float*)d_in[0];
    const float* k     = (const float*)d_in[1];
    const float* v     = (const float*)d_in[2];
    const float* wq    = (const float*)d_in[3];
    const float* wk    = (const float*)d_in[4];
    const float* wv    = (const float*)d_in[5];
    const float* wo    = (const float*)d_in[6];
    const float* gamma = (const float*)d_in[7];
    const float* beta  = (const float*)d_in[8];
    float* out = (float*)d_out;

    float* gtmp;
    __half *gxh, *gwth, *gph, *gpl, *goh;
    cudaGetSymbolAddress((void**)&gtmp, g_tmp);
    cudaGetSymbolAddress((void**)&gxh,  g_xh);
    cudaGetSymbolAddress((void**)&gwth, g_wth);
    cudaGetSymbolAddress((void**)&gph,  g_ph);
    cudaGetSymbolAddress((void**)&gpl,  g_pl);
    cudaGetSymbolAddress((void**)&goh,  g_oh);

    cudaFuncSetAttribute(gemm_tc,
                         cudaFuncAttributeMaxDynamicSharedMemorySize, GEMM_SMEM);
    cudaFuncSetAttribute(attn_tc,
                         cudaFuncAttributeMaxDynamicSharedMemorySize, ATTN2_SMEM);

    const dim3 blk256(256);
    const dim3 ggemm(Dd / 128, MS / 128);     // (8, 32)

    // conversions up front (2 launches)
    conv_wt_all<<<dim3(Dd / 32, Dd / 32, 4), blk256>>>(wq, wk, wv, wo, gwth);
    conv_act_all<<<dim3(MS * Dd / 4 / 256, 1, 3), blk256>>>(q, k, v, gxh);

    // Q/K/V projections (single-product; split fp16 outputs for Q-lo)
    gemm_tc<<<ggemm, blk256, GEMM_SMEM>>>(
        gxh,           gwth,           nullptr, nullptr, gph,           gpl);
    gemm_tc<<<ggemm, blk256, GEMM_SMEM>>>(
        gxh + PSZ,     gwth + WSZ,     nullptr, nullptr, gph + PSZ,     gpl + PSZ);
    gemm_tc<<<ggemm, blk256, GEMM_SMEM>>>(
        gxh + 2 * PSZ, gwth + 2 * WSZ, nullptr, nullptr, gph + 2 * PSZ, gpl + 2 * PSZ);

    // flash attention: Q hi+lo, K hi, V hi -> O (fp16)
    attn_tc<<<dim3(Ss / 128, Hh, Bb), blk256, ATTN2_SMEM>>>(
        gph, gpl, gph + PSZ, gph + 2 * PSZ, goh);

    // output projection + residual (fp32 out), single-product
    gemm_tc<<<ggemm, blk256, GEMM_SMEM>>>(
        goh, gwth + 3 * WSZ, q, gtmp, nullptr, nullptr);

    // LayerNorm
    ln_kernel<<<MS, blk256>>>(gtmp, gamma, beta, out);
}

// round 13
// speedup vs baseline: 2.4350x; 1.2457x over previous
#include <cuda_runtime.h>
#include <cuda_fp16.h>
#include <cstdint>

// Problem constants
#define Bb  2
#define Ss  2048
#define Dd  1024
#define Hh  16
#define HDd 64
#define MS  (Bb*Ss)          // 4096 rows
#define LN_EPS 1e-5f
#define GK 1024
#define PSZ ((size_t)MS * Dd)
#define WSZ ((size_t)Dd * Dd)

// ---------------------------------------------------------------------------
// Scratch (device globals)
// ---------------------------------------------------------------------------
__device__ float g_tmp[MS*Dd];                 // pre-LN
__device__ __half g_xh[3*MS*Dd];               // staged inputs (q,k,v planes, fp16)
__device__ __half g_wth[4*Dd*Dd];              // W^T [N][K] fp16 (wq,wk,wv,wo)
__device__ __half g_ph[3*MS*Dd];               // projections (Q,K,V planes, fp16)
__device__ __half g_oh[MS*Dd];                 // attention out (fp16)

// ---------------------------------------------------------------------------
// Helpers
// ---------------------------------------------------------------------------
__device__ __forceinline__ uint32_t smem_u32(const void* p) {
    uint32_t a;
    asm("{ .reg .u64 t; cvta.to.shared.u64 t, %1; cvt.u32.u64 %0, t; }"
        : "=r"(a) : "l"(p));
    return a;
}
__device__ __forceinline__ void cpa16(uint32_t s, const void* g) {
    asm volatile("cp.async.cg.shared.global [%0], [%1], 16;" :: "r"(s), "l"(g));
}
#define CPA_COMMIT() asm volatile("cp.async.commit_group;" ::: "memory")
#define CPA_WAIT0()  asm volatile("cp.async.wait_group 0;" ::: "memory")
#define CPA_WAIT1()  asm volatile("cp.async.wait_group 1;" ::: "memory")

__device__ __forceinline__ void ldm4(uint32_t a, uint32_t r[4]) {
    asm volatile("ldmatrix.sync.aligned.m8n8.x4.shared.b16 {%0,%1,%2,%3}, [%4];"
                 : "=r"(r[0]), "=r"(r[1]), "=r"(r[2]), "=r"(r[3]) : "r"(a));
}
__device__ __forceinline__ void ldm4t(uint32_t a, uint32_t r[4]) {
    asm volatile("ldmatrix.sync.aligned.m8n8.x4.trans.shared.b16 {%0,%1,%2,%3}, [%4];"
                 : "=r"(r[0]), "=r"(r[1]), "=r"(r[2]), "=r"(r[3]) : "r"(a));
}
// fp16 HMMA, fp32 accumulate
__device__ __forceinline__ void mma16816(float d[4], const uint32_t a[4],
                                         uint32_t b0, uint32_t b1) {
    asm volatile(
        "mma.sync.aligned.m16n8k16.row.col.f32.f16.f16.f32 "
        "{%0,%1,%2,%3}, {%4,%5,%6,%7}, {%8,%9}, {%0,%1,%2,%3};"
        : "+f"(d[0]), "+f"(d[1]), "+f"(d[2]), "+f"(d[3])
        : "r"(a[0]), "r"(a[1]), "r"(a[2]), "r"(a[3]), "r"(b0), "r"(b1));
}
__device__ __forceinline__ uint32_t pack_h2(float x, float y) {
    __half hx = __float2half_rn(x), hy = __float2half_rn(y);
    return (uint32_t)__half_as_ushort(hx) | ((uint32_t)__half_as_ushort(hy) << 16);
}

// ---------------------------------------------------------------------------
// fp16 single-product HMMA GEMM: C = A @ Wh (+resid)  [R12 frozen]
// 256 threads, 128x128 CTA tile, 64x32 warp tile, 2 CTAs/SM.
// ---------------------------------------------------------------------------
#define GEMM_SMEM 40960

__global__ __launch_bounds__(256, 2)
void gemm_tc(const __half* __restrict__ Ah,
             const __half* __restrict__ Wh,
             const float* __restrict__ resid, float* __restrict__ C,
             __half* __restrict__ OH)
{
    extern __shared__ __half S[];
    const int tid  = threadIdx.x;
    const int lane = tid & 31;
    const int wid  = tid >> 5;            // 0..7
    const int bm = blockIdx.y * 128;
    const int bn = blockIdx.x * 128;
    const int wm = (wid & 1) * 64;
    const int wn = (wid >> 1) * 32;

    const __half* gA = Ah + (size_t)bm * GK;
    const __half* gB = Wh + (size_t)bn * GK;

    const uint32_t sbase = smem_u32(S);

    float d[4][4][4];
    #pragma unroll
    for (int i = 0; i < 4; i++)
        #pragma unroll
        for (int j = 0; j < 4; j++)
            #pragma unroll
            for (int e = 0; e < 4; e++) d[i][j][e] = 0.f;

    const uint32_t acb_row = (uint32_t)(lane & 15);
    const uint32_t acb_col = (uint32_t)((lane >> 4) * 8);

    {
        #pragma unroll
        for (int it = 0; it < 2; it++) {
            int f = tid + it * 256;
            int r = f >> 2;
            int u = f & 3;
            uint32_t so = sbase + (uint32_t)(r * 40 + u * 8) * 2;
            size_t go = (size_t)r * GK + u * 8;
            cpa16(so,          gA + go);
            cpa16(so + 10240u, gB + go);
        }
        CPA_COMMIT();
        CPA_WAIT0();
        __syncthreads();
    }

    for (int ic = 0; ic < 32; ic++) {
        const int st = ic & 1;
        if (ic + 1 < 32) {
            const int k0 = (ic + 1) * 32;
            const uint32_t sb2 = sbase + (uint32_t)((st ^ 1) * 20480);
            #pragma unroll
            for (int it = 0; it < 2; it++) {
                int f = tid + it * 256;
                int r = f >> 2;
                int u = f & 3;
                uint32_t so = sb2 + (uint32_t)(r * 40 + u * 8) * 2;
                size_t go = (size_t)r * GK + k0 + u * 8;
                cpa16(so,          gA + go);
                cpa16(so + 10240u, gB + go);
            }
        }
        CPA_COMMIT();

        const uint32_t sb = sbase + (uint32_t)(st * 20480);
        #pragma unroll
        for (int ks = 0; ks < 2; ks++) {
            const uint32_t cb = (uint32_t)(ks * 16) * 2 + acb_col * 2;

            uint32_t ah[4][4], bh[2][4];
            #pragma unroll
            for (int i = 0; i < 4; i++)
                ldm4(sb + (uint32_t)((wm + i * 16) + acb_row) * 80u + cb, ah[i]);
            #pragma unroll
            for (int nb = 0; nb < 2; nb++)
                ldm4(sb + 10240u + (uint32_t)((wn + nb * 16) + acb_row) * 80u + cb, bh[nb]);

            #pragma unroll
            for (int i = 0; i < 4; i++)
                #pragma unroll
                for (int nb = 0; nb < 2; nb++) {
                    mma16816(d[i][2*nb],     ah[i], bh[nb][0], bh[nb][2]);
                    mma16816(d[i][2*nb + 1], ah[i], bh[nb][1], bh[nb][3]);
                }
        }
        CPA_WAIT0();
        __syncthreads();
    }

    const int er = bm + wm + (lane >> 2);
    const int ec = bn + wn + (lane & 3) * 2;
    #pragma unroll
    for (int i = 0; i < 4; i++) {
        const int r1 = er + i * 16;
        #pragma unroll
        for (int jj = 0; jj < 4; jj++) {
            const int c = ec + jj * 8;
            size_t o0 = (size_t)r1 * GK + c;
            size_t o1 = (size_t)(r1 + 8) * GK + c;
            if (OH) {
                *(uint32_t*)(OH + o0) = pack_h2(d[i][jj][0], d[i][jj][1]);
                *(uint32_t*)(OH + o1) = pack_h2(d[i][jj][2], d[i][jj][3]);
            } else {
                float2 v0 = make_float2(d[i][jj][0], d[i][jj][1]);
                float2 v1 = make_float2(d[i][jj][2], d[i][jj][3]);
                if (resid) {
                    float2 q0 = *(const float2*)(resid + o0);
                    float2 q1 = *(const float2*)(resid + o1);
                    v0.x += q0.x; v0.y += q0.y;
                    v1.x += q1.x; v1.y += q1.y;
                }
                *(float2*)(C + o0) = v0;
                *(float2*)(C + o1) = v1;
            }
        }
    }
}

// ---------------------------------------------------------------------------
// fp32 -> fp16; grid.z selects source (q,k,v) -> plane z
// ---------------------------------------------------------------------------
__global__ __launch_bounds__(256) void conv_act_all(
    const float* __restrict__ X0, const float* __restrict__ X1,
    const float* __restrict__ X2, __half* __restrict__ H)
{
    const int z = blockIdx.z;
    const float* X = (z == 0) ? X0 : (z == 1) ? X1 : X2;
    size_t i = (size_t)blockIdx.x * 256 + threadIdx.x;
    float4 v = ((const float4*)X)[i];
    __half h[4];
    h[0] = __float2half_rn(v.x);
    h[1] = __float2half_rn(v.y);
    h[2] = __float2half_rn(v.z);
    h[3] = __float2half_rn(v.w);
    uint64_t hp;
    memcpy(&hp, h, 8);
    ((uint64_t*)H)[(size_t)z * (PSZ / 4) + i] = hp;
}

// ---------------------------------------------------------------------------
// W [K][N] fp32 -> W^T fp16 [N][K]; grid.z selects (wq,wk,wv,wo)
// ---------------------------------------------------------------------------
__global__ __launch_bounds__(256) void conv_wt_all(
    const float* __restrict__ W0, const float* __restrict__ W1,
    const float* __restrict__ W2, const float* __restrict__ W3,
    __half* __restrict__ TH)
{
    __shared__ float t[32][33];
    const int z = blockIdx.z;
    const float* W = (z == 0) ? W0 : (z == 1) ? W1 : (z == 2) ? W2 : W3;
    const size_t zw = (size_t)z * WSZ;
    const int bxn = blockIdx.x * 32;
    const int byk = blockIdx.y * 32;
    const int tx = threadIdx.x & 31;
    const int ty4 = (threadIdx.x >> 5) * 4;

    #pragma unroll
    for (int j = 0; j < 4; j++)
        t[ty4 + j][tx] = W[(size_t)(byk + ty4 + j) * Dd + bxn + tx];
    __syncthreads();

    #pragma unroll
    for (int j = 0; j < 4; j++)
        TH[zw + (size_t)(bxn + ty4 + j) * Dd + byk + tx] =
            __float2half_rn(t[tx][ty4 + j]);
}

// ---------------------------------------------------------------------------
// fp16 HMMA flash attention (causal), single-product:
//   S = Qh·Kh,  O = Ph·Vh.
// Q persistent in SMEM [0, 18432); K/V double-buffer above.
// ---------------------------------------------------------------------------
#define AT_ROWB    144
#define AT_TILE_B  (64 * AT_ROWB)          // 9216
#define AT_KVSTG_B (2 * AT_TILE_B)         // 18432: Kh + Vh
#define AT_Q_B     18432                   // Q only
#define ATTN2_SMEM (AT_Q_B + 2 * AT_KVSTG_B)   // 55296
#define CS 0.18033688011112042f            // log2(e)/8

__global__ __launch_bounds__(256, 2) void attn_tc(
    const __half* __restrict__ Qh,
    const __half* __restrict__ Kh, const __half* __restrict__ Vh,
    __half* __restrict__ Oh)
{
    extern __shared__ char smc[];
    const int tid = threadIdx.x;
    const int lane = tid & 31;
    const int w = tid >> 5;
    const int bx = blockIdx.x, h = blockIdx.y, b = blockIdx.z;
    const int q0 = bx * 128;
    const uint32_t sb = smem_u32(smc);
    const uint32_t kvb = sb + AT_Q_B;
    const size_t headoff = (size_t)b * Ss * Dd + (size_t)h * HDd;

    // ---- Q tile -> persistent SMEM
    {
        const __half* gq = Qh + headoff + (size_t)q0 * Dd;
        #pragma unroll
        for (int it = 0; it < 4; it++) {
            int f = tid + it * 256;          // 0..1023
            int r = f >> 3, ch = f & 7;
            uint32_t so = sb + (uint32_t)(r * AT_ROWB + ch * 16);
            cpa16(so, gq + (size_t)r * Dd + ch * 8);
        }
        CPA_COMMIT();
        CPA_WAIT0();
    }
    __syncthreads();

    const uint32_t qlb = sb + (uint32_t)((16 * w + (lane & 15)) * AT_ROWB
                                         + (lane >> 4) * 16);

    float oacc[8][4];
    #pragma unroll
    for (int i = 0; i < 8; i++)
        #pragma unroll
        for (int e = 0; e < 4; e++) oacc[i][e] = 0.f;
    float m0 = -1e30f, m1 = -1e30f, l0 = 0.f, l1 = 0.f;
    const int r0g = q0 + 16 * w + (lane >> 2);
    const int r1g = r0g + 8;

    const int nkt = 2 * bx + 2;
    const __half *gkh = Kh + headoff, *gvh = Vh + headoff;

    // prologue: KV tile 0 -> stage 0
    #pragma unroll
    for (int it = 0; it < 2; it++) {
        int f = tid + it * 256;              // 0..511
        int r = f >> 3, ch = f & 7;
        uint32_t so = kvb + (uint32_t)(r * AT_ROWB + ch * 16);
        size_t go = (size_t)r * Dd + ch * 8;
        cpa16(so,             gkh + go);
        cpa16(so + AT_TILE_B, gvh + go);
    }
    CPA_COMMIT();

    for (int kt = 0; kt < nkt; kt++) {
        __syncthreads();
        if (kt + 1 < nkt) {
            const uint32_t st2 = kvb + (uint32_t)(((kt + 1) & 1) * AT_KVSTG_B);
            const size_t kb = (size_t)(kt + 1) * 64 * Dd;
            #pragma unroll
            for (int it = 0; it < 2; it++) {
                int f = tid + it * 256;
                int r = f >> 3, ch = f & 7;
                uint32_t so = st2 + (uint32_t)(r * AT_ROWB + ch * 16);
                size_t go = kb + (size_t)r * Dd + ch * 8;
                cpa16(so,             gkh + go);
                cpa16(so + AT_TILE_B, gvh + go);
            }
            CPA_COMMIT();
            CPA_WAIT1();
        } else {
            CPA_WAIT0();
        }
        __syncthreads();

        const int k0 = kt * 64;
        const bool active = (k0 <= q0 + 16 * w + 15);   // warp-uniform
        if (active) {
            const uint32_t stg = kvb + (uint32_t)((kt & 1) * AT_KVSTG_B);
            float sacc[8][4];
            #pragma unroll
            for (int i = 0; i < 8; i++)
                #pragma unroll
                for (int e = 0; e < 4; e++) sacc[i][e] = 0.f;

            const uint32_t lb = stg + (uint32_t)((lane & 15) * AT_ROWB
                                                 + (lane >> 4) * 16);
            #pragma unroll
            for (int c = 0; c < 4; c++) {
                uint32_t qh4[4];
                ldm4(qlb + (uint32_t)(c * 32), qh4);
                #pragma unroll
                for (int g = 0; g < 4; g++) {
                    uint32_t kh4[4];
                    ldm4(lb + (uint32_t)(g * 16 * AT_ROWB + c * 32), kh4);
                    mma16816(sacc[2*g],   qh4, kh4[0], kh4[2]);
                    mma16816(sacc[2*g+1], qh4, kh4[1], kh4[3]);
                }
            }

            if (k0 + 63 > q0 + 16 * w) {
                #pragma unroll
                for (int nb = 0; nb < 8; nb++) {
                    int col = k0 + nb * 8 + (lane & 3) * 2;
                    if (col     > r0g) sacc[nb][0] = -1e30f;
                    if (col + 1 > r0g) sacc[nb][1] = -1e30f;
                    if (col     > r1g) sacc[nb][2] = -1e30f;
                    if (col + 1 > r1g) sacc[nb][3] = -1e30f;
                }
            }

            float mx0 = -1e30f, mx1 = -1e30f;
            #pragma unroll
            for (int nb = 0; nb < 8; nb++) {
                mx0 = fmaxf(mx0, fmaxf(sacc[nb][0], sacc[nb][1]));
                mx1 = fmaxf(mx1, fmaxf(sacc[nb][2], sacc[nb][3]));
            }
            mx0 = fmaxf(mx0, __shfl_xor_sync(0xffffffffu, mx0, 1));
            mx0 = fmaxf(mx0, __shfl_xor_sync(0xffffffffu, mx0, 2));
            mx1 = fmaxf(mx1, __shfl_xor_sync(0xffffffffu, mx1, 1));
            mx1 = fmaxf(mx1, __shfl_xor_sync(0xffffffffu, mx1, 2));
            const float nm0 = fmaxf(m0, mx0), nm1 = fmaxf(m1, mx1);
            const float a0 = exp2f((m0 - nm0) * CS);
            const float a1 = exp2f((m1 - nm1) * CS);
            m0 = nm0; m1 = nm1;
            const float c0 = nm0 * CS, c1 = nm1 * CS;
            float s0 = 0.f, s1 = 0.f;
            #pragma unroll
            for (int nb = 0; nb < 8; nb++) {
                float p0 = exp2f(fmaf(sacc[nb][0], CS, -c0));
                float p1 = exp2f(fmaf(sacc[nb][1], CS, -c0));
                float p2 = exp2f(fmaf(sacc[nb][2], CS, -c1));
                float p3 = exp2f(fmaf(sacc[nb][3], CS, -c1));
                sacc[nb][0] = p0; sacc[nb][1] = p1;
                sacc[nb][2] = p2; sacc[nb][3] = p3;
                s0 += p0 + p1;
                s1 += p2 + p3;
            }
            s0 += __shfl_xor_sync(0xffffffffu, s0, 1);
            s0 += __shfl_xor_sync(0xffffffffu, s0, 2);
            s1 += __shfl_xor_sync(0xffffffffu, s1, 1);
            s1 += __shfl_xor_sync(0xffffffffu, s1, 2);
            l0 = l0 * a0 + s0;
            l1 = l1 * a1 + s1;
            #pragma unroll
            for (int i = 0; i < 8; i++) {
                oacc[i][0] *= a0; oacc[i][1] *= a0;
                oacc[i][2] *= a1; oacc[i][3] *= a1;
            }

            // O += Ph · Vh
            #pragma unroll
            for (int j = 0; j < 4; j++) {
                uint32_t pa[4];
                pa[0] = pack_h2(sacc[2*j][0],   sacc[2*j][1]);
                pa[1] = pack_h2(sacc[2*j][2],   sacc[2*j][3]);
                pa[2] = pack_h2(sacc[2*j+1][0], sacc[2*j+1][1]);
                pa[3] = pack_h2(sacc[2*j+1][2], sacc[2*j+1][3]);
                const uint32_t vb = stg + AT_TILE_B
                    + (uint32_t)((16 * j + (lane & 15)) * AT_ROWB + (lane >> 4) * 16);
                #pragma unroll
                for (int dp = 0; dp < 4; dp++) {
                    uint32_t vh4[4];
                    ldm4t(vb + (uint32_t)(dp * 32), vh4);
                    mma16816(oacc[2*dp],   pa, vh4[0], vh4[1]);
                    mma16816(oacc[2*dp+1], pa, vh4[2], vh4[3]);
                }
            }
        }
    }

    const float i0 = 1.f / l0, i1 = 1.f / l1;
    const size_t ro0 = (size_t)b * Ss * Dd + (size_t)r0g * Dd + (size_t)h * HDd;
    const size_t ro1 = ro0 + 8 * Dd;
    #pragma unroll
    for (int nb = 0; nb < 8; nb++) {
        const int dcol = nb * 8 + (lane & 3) * 2;
        *(uint32_t*)(Oh + ro0 + dcol) = pack_h2(oacc[nb][0] * i0, oacc[nb][1] * i0);
        *(uint32_t*)(Oh + ro1 + dcol) = pack_h2(oacc[nb][2] * i1, oacc[nb][3] * i1);
    }
}

// ---------------------------------------------------------------------------
// LayerNorm over last dim (1024)
// ---------------------------------------------------------------------------
__global__ __launch_bounds__(256) void ln_kernel(
    const float* __restrict__ X, const float* __restrict__ gamma,
    const float* __restrict__ beta, float* __restrict__ Y)
{
    const int row = blockIdx.x;
    const int t = threadIdx.x;
    const float4 v = ((const float4*)(X + (size_t)row * Dd))[t];

    float s  = v.x + v.y + v.z + v.w;
    float ss = v.x * v.x + v.y * v.y + v.z * v.z + v.w * v.w;
    #pragma unroll
    for (int o = 16; o > 0; o >>= 1) {
        s  += __shfl_xor_sync(0xffffffffu, s,  o);
        ss += __shfl_xor_sync(0xffffffffu, ss, o);
    }
    __shared__ float sh[8][2];
    if ((t & 31) == 0) { sh[t >> 5][0] = s; sh[t >> 5][1] = ss; }
    __syncthreads();
    float ts = 0.f, tss = 0.f;
    #pragma unroll
    for (int i = 0; i < 8; i++) { ts += sh[i][0]; tss += sh[i][1]; }

    const float mu  = ts * (1.0f / Dd);
    const float var = tss * (1.0f / Dd) - mu * mu;
    const float inv = rsqrtf(var + LN_EPS);

    const float4 gg = ((const float4*)gamma)[t];
    const float4 bb = ((const float4*)beta)[t];
    float4 y;
    y.x = (v.x - mu) * inv * gg.x + bb.x;
    y.y = (v.y - mu) * inv * gg.y + bb.y;
    y.z = (v.z - mu) * inv * gg.z + bb.z;
    y.w = (v.w - mu) * inv * gg.w + bb.w;
    ((float4*)(Y + (size_t)row * Dd))[t] = y;
}

// ---------------------------------------------------------------------------
// Launch. Inputs: q, k, v, wq, wk, wv, wo, gamma, beta, mask (causal; unused).
// ---------------------------------------------------------------------------
extern "C" void kernel_launch(void* const* d_in, const int* in_sizes, int n_in,
                              void* d_out, int out_size)
{
    const float* q     = (const float*)d_in[0];
    const float* k     = (const float*)d_in[1];
    const float* v     = (const float*)d_in[2];
    const float* wq    = (const float*)d_in[3];
    const float* wk    = (const float*)d_in[4];
    const float* wv    = (const float*)d_in[5];
    const float* wo    = (const float*)d_in[6];
    const float* gamma = (const float*)d_in[7];
    const float* beta  = (const float*)d_in[8];
    float* out = (float*)d_out;

    float* gtmp;
    __half *gxh, *gwth, *gph, *goh;
    cudaGetSymbolAddress((void**)&gtmp, g_tmp);
    cudaGetSymbolAddress((void**)&gxh,  g_xh);
    cudaGetSymbolAddress((void**)&gwth, g_wth);
    cudaGetSymbolAddress((void**)&gph,  g_ph);
    cudaGetSymbolAddress((void**)&goh,  g_oh);

    cudaFuncSetAttribute(gemm_tc,
                         cudaFuncAttributeMaxDynamicSharedMemorySize, GEMM_SMEM);
    cudaFuncSetAttribute(attn_tc,
                         cudaFuncAttributeMaxDynamicSharedMemorySize, ATTN2_SMEM);

    const dim3 blk256(256);
    const dim3 ggemm(Dd / 128, MS / 128);     // (8, 32)

    // conversions up front (2 launches)
    conv_wt_all<<<dim3(Dd / 32, Dd / 32, 4), blk256>>>(wq, wk, wv, wo, gwth);
    conv_act_all<<<dim3(MS * Dd / 4 / 256, 1, 3), blk256>>>(q, k, v, gxh);

    // Q/K/V projections (single-product, fp16 outputs)
    gemm_tc<<<ggemm, blk256, GEMM_SMEM>>>(
        gxh,           gwth,           nullptr, nullptr, gph);
    gemm_tc<<<ggemm, blk256, GEMM_SMEM>>>(
        gxh + PSZ,     gwth + WSZ,     nullptr, nullptr, gph + PSZ);
    gemm_tc<<<ggemm, blk256, GEMM_SMEM>>>(
        gxh + 2 * PSZ, gwth + 2 * WSZ, nullptr, nullptr, gph + 2 * PSZ);

    // flash attention: single-product S and O
    attn_tc<<<dim3(Ss / 128, Hh, Bb), blk256, ATTN2_SMEM>>>(
        gph, gph + PSZ, gph + 2 * PSZ, goh);

    // output projection + residual (fp32 out)
    gemm_tc<<<ggemm, blk256, GEMM_SMEM>>>(
        goh, gwth + 3 * WSZ, q, gtmp, nullptr);

    // LayerNorm
    ln_kernel<<<MS, blk256>>>(gtmp, gamma, beta, out);
}